// round 14
// baseline (speedup 1.0000x reference)
#include <cuda_runtime.h>
#include <math.h>
#include <stdint.h>

#define MROWS 4096
#define DMODEL 1024
#define QPROJ 512
#define KVPROJ 1024
#define NH 16
#define DH 64
#define SEQ 2048
#define BATCH 2
#define EPS 1e-5f
#define LOG2E 1.44269504088896340736f

// ---------------- scratch (no allocations allowed) ----------------
__device__ float g_xq  [MROWS * DMODEL];
__device__ float g_xkv [MROWS * DMODEL];
__device__ float g_tq  [MROWS * QPROJ];
__device__ float g_cq  [MROWS * QPROJ];
__device__ float g_Q   [MROWS * DMODEL];
__device__ float g_tkv [MROWS * KVPROJ];
__device__ float g_ckv [MROWS * KVPROJ];
__device__ float g_KV  [MROWS * 2 * DMODEL];
__device__ float g_attn[MROWS * DMODEL];
__device__ float g_woT [DMODEL * DMODEL];   // wo transposed: woT[k][n] = wo[n][k]

// ---------------- tf32 helpers ----------------
__device__ __forceinline__ unsigned f2tf(float f) {
    unsigned u; asm("cvt.rna.tf32.f32 %0, %1;" : "=r"(u) : "f"(f)); return u;
}
__device__ __forceinline__ uint4 cvt4(float4 v) {
    uint4 u; u.x = f2tf(v.x); u.y = f2tf(v.y); u.z = f2tf(v.z); u.w = f2tf(v.w); return u;
}
__device__ __forceinline__ float ex2(float x) {
    float r; asm("ex2.approx.f32 %0, %1;" : "=f"(r) : "f"(x)); return r;
}
__device__ __forceinline__ void mma_tf32(float c[4], unsigned a0, unsigned a1, unsigned a2, unsigned a3,
                                         unsigned b0, unsigned b1) {
    asm volatile(
        "mma.sync.aligned.m16n8k8.row.col.f32.tf32.tf32.f32 "
        "{%0,%1,%2,%3},{%4,%5,%6,%7},{%8,%9},{%0,%1,%2,%3};"
        : "+f"(c[0]), "+f"(c[1]), "+f"(c[2]), "+f"(c[3])
        : "r"(a0), "r"(a1), "r"(a2), "r"(a3), "r"(b0), "r"(b1));
}

// ---------------- block reduction (sum, sumsq), 256 threads ----------------
__device__ __forceinline__ float2 block_reduce2(float s, float q, float* sh) {
    #pragma unroll
    for (int o = 16; o; o >>= 1) {
        s += __shfl_xor_sync(0xffffffffu, s, o);
        q += __shfl_xor_sync(0xffffffffu, q, o);
    }
    int w = threadIdx.x >> 5;
    if ((threadIdx.x & 31) == 0) { sh[w] = s; sh[8 + w] = q; }
    __syncthreads();
    if (threadIdx.x < 32) {
        s = (threadIdx.x < 8) ? sh[threadIdx.x] : 0.f;
        q = (threadIdx.x < 8) ? sh[8 + threadIdx.x] : 0.f;
        #pragma unroll
        for (int o = 4; o; o >>= 1) {
            s += __shfl_xor_sync(0xffffffffu, s, o);
            q += __shfl_xor_sync(0xffffffffu, q, o);
        }
        if (threadIdx.x == 0) { sh[16] = s; sh[17] = q; }
    }
    __syncthreads();
    return make_float2(sh[16], sh[17]);
}

// ---------------- fused dual pre-LN (y=0) + wo transpose (y=1) --------------
__global__ void __launch_bounds__(256) prenorm_trans_kernel(
    const float* __restrict__ x,
    const float* __restrict__ pg, const float* __restrict__ pb,
    const float* __restrict__ kg, const float* __restrict__ kb,
    float* __restrict__ xq, float* __restrict__ xkv,
    const float* __restrict__ wo, float* __restrict__ woT)
{
    __shared__ float sh[32 * 33];
    if (blockIdx.y == 1) {
        int idx = blockIdx.x;
        if (idx >= (DMODEL / 32) * (DMODEL / 32)) return;
        int i0 = (idx & (DMODEL / 32 - 1)) * 32;   // k block
        int j0 = (idx / (DMODEL / 32)) * 32;       // n block
        int tx = threadIdx.x & 31, ty = threadIdx.x >> 5;
        #pragma unroll
        for (int j = 0; j < 4; j++)
            sh[(ty + j * 8) * 33 + tx] = wo[(size_t)(j0 + ty + j * 8) * DMODEL + i0 + tx];
        __syncthreads();
        #pragma unroll
        for (int j = 0; j < 4; j++)
            woT[(size_t)(i0 + ty + j * 8) * DMODEL + j0 + tx] = sh[tx * 33 + ty + j * 8];
        return;
    }
    int row = blockIdx.x;
    int i = threadIdx.x * 4;
    const float* xr = x + (size_t)row * DMODEL;
    float4 v = *(const float4*)&xr[i];
    float s = v.x + v.y + v.z + v.w;
    float q = v.x * v.x + v.y * v.y + v.z * v.z + v.w * v.w;
    float2 r = block_reduce2(s, q, sh);
    float mu = r.x * (1.f / DMODEL);
    float var = r.y * (1.f / DMODEL) - mu * mu;
    float inv = rsqrtf(var + EPS);
    float4 g1 = *(const float4*)&pg[i], b1 = *(const float4*)&pb[i];
    float4 g2 = *(const float4*)&kg[i], b2 = *(const float4*)&kb[i];
    float4 n = make_float4((v.x - mu) * inv, (v.y - mu) * inv, (v.z - mu) * inv, (v.w - mu) * inv);
    *(float4*)&xq [(size_t)row * DMODEL + i] =
        make_float4(n.x * g1.x + b1.x, n.y * g1.y + b1.y, n.z * g1.z + b1.z, n.w * g1.w + b1.w);
    *(float4*)&xkv[(size_t)row * DMODEL + i] =
        make_float4(n.x * g2.x + b2.x, n.y * g2.y + b2.y, n.z * g2.z + b2.z, n.w * g2.w + b2.w);
}

// ---------------- row LN core + batched pair --------------------------------
__device__ __forceinline__ void ln_core(
    const float* __restrict__ x, const float* __restrict__ g,
    const float* __restrict__ b, float* __restrict__ y, int N, float* sh)
{
    int row = blockIdx.x;
    const float* xr = x + (size_t)row * N;
    float s = 0.f, q = 0.f;
    for (int i = threadIdx.x * 4; i < N; i += 1024) {
        float4 v = *(const float4*)&xr[i];
        s += v.x + v.y + v.z + v.w;
        q += v.x * v.x + v.y * v.y + v.z * v.z + v.w * v.w;
    }
    float2 r = block_reduce2(s, q, sh);
    float mu = r.x / N;
    float var = r.y / N - mu * mu;
    float inv = rsqrtf(var + EPS);
    for (int i = threadIdx.x * 4; i < N; i += 1024) {
        float4 v = *(const float4*)&xr[i];
        float4 gv = *(const float4*)&g[i], bv = *(const float4*)&b[i];
        *(float4*)&y[(size_t)row * N + i] = make_float4(
            (v.x - mu) * inv * gv.x + bv.x, (v.y - mu) * inv * gv.y + bv.y,
            (v.z - mu) * inv * gv.z + bv.z, (v.w - mu) * inv * gv.w + bv.w);
    }
}

__global__ void __launch_bounds__(256) ln_pair(
    const float* __restrict__ x0, const float* __restrict__ g0,
    const float* __restrict__ b0, float* __restrict__ y0, int N0,
    const float* __restrict__ x1, const float* __restrict__ g1,
    const float* __restrict__ b1, float* __restrict__ y1, int N1)
{
    __shared__ float sh[18];
    if (blockIdx.y == 0) ln_core(x0, g0, b0, y0, N0, sh);
    else                 ln_core(x1, g1, b1, y1, N1, sh);
}

// ---------------- tf32 tensor-core GEMM core (R5 body) ----------------------
#define GBM 128
#define GBN 128
#define GBK 32
#define ASTRIDE 516
#define BSTRIDE 136

template <bool ROUND>
__device__ __forceinline__ void gemm_core(
    unsigned* As, unsigned* Bs,
    const float* __restrict__ A, const float* __restrict__ B,
    float* __restrict__ C, int N, int K, float alpha)
{
    int tid = threadIdx.x;
    int m0 = blockIdx.y * GBM, n0 = blockIdx.x * GBN;
    int warp = tid >> 5, lane = tid & 31;
    int g = lane >> 2, t = lane & 3;
    int wm = (warp & 1) * 64, wn = (warp >> 1) * 32;

    int ar = tid >> 3, ac4 = tid & 7;
    int br = tid >> 5, bc4 = tid & 31;

    float4 ra[4], rb[4];

    auto loadT = [&](int k0) {
        #pragma unroll
        for (int i = 0; i < 4; i++)
            ra[i] = *(const float4*)&A[(size_t)(m0 + ar + 32 * i) * K + k0 + ac4 * 4];
        #pragma unroll
        for (int i = 0; i < 4; i++)
            rb[i] = *(const float4*)&B[(size_t)(k0 + br + 8 * i) * N + n0 + bc4 * 4];
    };
    auto storeT = [&]() {
        #pragma unroll
        for (int i = 0; i < 4; i++)
            *(uint4*)&As[ac4 * ASTRIDE + (ar + 32 * i) * 4] = cvt4(ra[i]);
        #pragma unroll
        for (int i = 0; i < 4; i++)
            *(uint4*)&Bs[(br + 8 * i) * BSTRIDE + bc4 * 4] = cvt4(rb[i]);
    };

    float c[4][4][4] = {};

    loadT(0);
    storeT();
    __syncthreads();

    for (int k0 = GBK; ; k0 += GBK) {
        bool more = k0 < K;
        if (more) loadT(k0);

        #pragma unroll
        for (int ks = 0; ks < GBK; ks += 8) {
            unsigned bf[4][2];
            #pragma unroll
            for (int nf = 0; nf < 4; nf++) {
                bf[nf][0] = Bs[(ks + t) * BSTRIDE + wn + nf * 8 + g];
                bf[nf][1] = Bs[(ks + t + 4) * BSTRIDE + wn + nf * 8 + g];
            }
            #pragma unroll
            for (int mf = 0; mf < 4; mf++) {
                int mb = wm + mf * 16 + g;
                int grp = ks >> 2;
                unsigned a0 = As[grp * ASTRIDE + mb * 4 + t];
                unsigned a1 = As[grp * ASTRIDE + (mb + 8) * 4 + t];
                unsigned a2 = As[(grp + 1) * ASTRIDE + mb * 4 + t];
                unsigned a3 = As[(grp + 1) * ASTRIDE + (mb + 8) * 4 + t];
                #pragma unroll
                for (int nf = 0; nf < 4; nf++)
                    mma_tf32(c[mf][nf], a0, a1, a2, a3, bf[nf][0], bf[nf][1]);
            }
        }
        if (!more) break;
        __syncthreads();
        storeT();
        __syncthreads();
    }

    auto outv = [&](float v) -> float {
        return ROUND ? __uint_as_float(f2tf(alpha * v)) : alpha * v;
    };
    #pragma unroll
    for (int mf = 0; mf < 4; mf++) {
        int r0 = m0 + wm + mf * 16 + g;
        #pragma unroll
        for (int nf = 0; nf < 4; nf++) {
            int cc = n0 + wn + nf * 8 + 2 * t;
            float2 lo = make_float2(outv(c[mf][nf][0]), outv(c[mf][nf][1]));
            float2 hi = make_float2(outv(c[mf][nf][2]), outv(c[mf][nf][3]));
            *(float2*)&C[(size_t)r0 * N + cc] = lo;
            *(float2*)&C[(size_t)(r0 + 8) * N + cc] = hi;
        }
    }
}

// solo gemm (wo, via pre-transposed woT -> non-TB path)
template <bool ROUND>
__global__ void __launch_bounds__(256) gemm_tf32(
    const float* __restrict__ A, const float* __restrict__ B,
    float* __restrict__ C, int N, int K, float alpha)
{
    __shared__ unsigned As[8 * ASTRIDE];
    __shared__ unsigned Bs[GBK * BSTRIDE];
    gemm_core<ROUND>(As, Bs, A, B, C, N, K, alpha);
}

// batched pair of independent GEMMs: blockIdx.z selects. Inactive x-tiles exit.
template <bool ROUND>
__global__ void __launch_bounds__(256, 2) gemm_pair(
    const float* __restrict__ A0, const float* __restrict__ B0, float* __restrict__ C0,
    int N0, int K0, float al0, int nx0,
    const float* __restrict__ A1, const float* __restrict__ B1, float* __restrict__ C1,
    int N1, int K1, float al1, int nx1)
{
    __shared__ unsigned As[8 * ASTRIDE];
    __shared__ unsigned Bs[GBK * BSTRIDE];
    if (blockIdx.z == 0) {
        if ((int)blockIdx.x >= nx0) return;
        gemm_core<ROUND>(As, Bs, A0, B0, C0, N0, K0, al0);
    } else {
        if ((int)blockIdx.x >= nx1) return;
        gemm_core<ROUND>(As, Bs, A1, B1, C1, N1, K1, al1);
    }
}

// ---------------- tensor-core causal flash attention, 128-query tiles --------
// 256 threads (8 warps); warp w owns rows w*16..w*16+15. Single 64-key K/V
// buffer (R5 load pattern). Only change vs R13: tile height 64 -> 128.
#define AQ_ROWS 128
#define QP_STR 68
#define KV_STR 76
#define ATT_SMEM ((AQ_ROWS * QP_STR + 2 * 64 * KV_STR) * 4)

extern __shared__ float att_sm[];

__global__ void __launch_bounds__(256) attn_tc_kernel(
    const float* __restrict__ Q, const float* __restrict__ KV, float* __restrict__ O)
{
    float* sQP = att_sm;                     // 128*68
    float* sK  = sQP + AQ_ROWS * QP_STR;     // 64*76
    float* sV  = sK  + 64 * KV_STR;          // 64*76

    int tid = threadIdx.x, warp = tid >> 5, lane = tid & 31;
    int g = lane >> 2, t = lane & 3;
    int wm = warp * 16;
    int qt = (int)gridDim.x - 1 - (int)blockIdx.x;   // heavy tiles first
    int h = blockIdx.y, b = blockIdx.z;
    int qrow0 = qt * AQ_ROWS;
    int nch = 2 * qt + 2;

    // ---- load Q tile -> smem ----
    #pragma unroll
    for (int it = 0; it < 8; it++) {
        int idx = tid + it * 256;
        int r = idx >> 4, c4 = idx & 15;
        float4 v = *(const float4*)&Q[((size_t)(b * SEQ + qrow0 + r)) * DMODEL + h * DH + c4 * 4];
        *(float4*)&sQP[r * QP_STR + c4 * 4] = v;
    }
    __syncthreads();

    // ---- Q A-fragments in registers ----
    unsigned qa[8][4];
    #pragma unroll
    for (int ks = 0; ks < 8; ks++) {
        qa[ks][0] = __float_as_uint(sQP[(wm + g)     * QP_STR + ks * 8 + t]);
        qa[ks][1] = __float_as_uint(sQP[(wm + g + 8) * QP_STR + ks * 8 + t]);
        qa[ks][2] = __float_as_uint(sQP[(wm + g)     * QP_STR + ks * 8 + t + 4]);
        qa[ks][3] = __float_as_uint(sQP[(wm + g + 8) * QP_STR + ks * 8 + t + 4]);
    }
    __syncthreads();   // QP buffer free for P

    float m0 = -INFINITY, m1 = -INFINITY, l0 = 0.f, l1 = 0.f;
    float co[8][4] = {};

    for (int ch = 0; ch < nch; ch++) {
        // ---- load K/V chunk (256 threads x 4 iters, R5 pattern) ----
        #pragma unroll
        for (int it = 0; it < 4; it++) {
            int idx = tid + it * 256;
            int r = idx >> 4, c4 = idx & 15;
            size_t base = ((size_t)(b * SEQ + ch * 64 + r)) * (2 * DMODEL) + h * DH + c4 * 4;
            float4 k4 = *(const float4*)&KV[base];
            float4 v4 = *(const float4*)&KV[base + DMODEL];
            *(float4*)&sK[r * KV_STR + c4 * 4] = k4;
            *(float4*)&sV[r * KV_STR + c4 * 4] = v4;
        }
        __syncthreads();

        // ---- S = Q K^T (log2 domain) ----
        float s[8][4] = {};
        #pragma unroll
        for (int ks = 0; ks < 8; ks++) {
            #pragma unroll
            for (int nf = 0; nf < 8; nf++) {
                unsigned b0 = __float_as_uint(sK[(nf * 8 + g) * KV_STR + ks * 8 + t]);
                unsigned b1 = __float_as_uint(sK[(nf * 8 + g) * KV_STR + ks * 8 + t + 4]);
                mma_tf32(s[nf], qa[ks][0], qa[ks][1], qa[ks][2], qa[ks][3], b0, b1);
            }
        }

        // ---- causal mask (only last two chunks can touch the diagonal) ----
        if (ch >= 2 * qt) {
            int r0 = qrow0 + wm + g, r1 = r0 + 8;
            #pragma unroll
            for (int nf = 0; nf < 8; nf++) {
                int col = ch * 64 + nf * 8 + 2 * t;
                if (col     > r0) s[nf][0] = -1e30f;
                if (col + 1 > r0) s[nf][1] = -1e30f;
                if (col     > r1) s[nf][2] = -1e30f;
                if (col + 1 > r1) s[nf][3] = -1e30f;
            }
        }

        // ---- online softmax (base-2, quad-lane reductions) ----
        float mx0 = -1e30f, mx1 = -1e30f;
        #pragma unroll
        for (int nf = 0; nf < 8; nf++) {
            mx0 = fmaxf(mx0, fmaxf(s[nf][0], s[nf][1]));
            mx1 = fmaxf(mx1, fmaxf(s[nf][2], s[nf][3]));
        }
        mx0 = fmaxf(mx0, __shfl_xor_sync(0xffffffffu, mx0, 1));
        mx0 = fmaxf(mx0, __shfl_xor_sync(0xffffffffu, mx0, 2));
        mx1 = fmaxf(mx1, __shfl_xor_sync(0xffffffffu, mx1, 1));
        mx1 = fmaxf(mx1, __shfl_xor_sync(0xffffffffu, mx1, 2));
        float nm0 = fmaxf(m0, mx0), nm1 = fmaxf(m1, mx1);
        float sc0 = ex2(m0 - nm0), sc1 = ex2(m1 - nm1);
        m0 = nm0; m1 = nm1;
        float sum0 = 0.f, sum1 = 0.f;
        #pragma unroll
        for (int nf = 0; nf < 8; nf++) {
            s[nf][0] = ex2(s[nf][0] - m0); sum0 += s[nf][0];
            s[nf][1] = ex2(s[nf][1] - m0); sum0 += s[nf][1];
            s[nf][2] = ex2(s[nf][2] - m1); sum1 += s[nf][2];
            s[nf][3] = ex2(s[nf][3] - m1); sum1 += s[nf][3];
        }
        sum0 += __shfl_xor_sync(0xffffffffu, sum0, 1);
        sum0 += __shfl_xor_sync(0xffffffffu, sum0, 2);
        sum1 += __shfl_xor_sync(0xffffffffu, sum1, 1);
        sum1 += __shfl_xor_sync(0xffffffffu, sum1, 2);
        l0 = l0 * sc0 + sum0;
        l1 = l1 * sc1 + sum1;
        #pragma unroll
        for (int nf = 0; nf < 8; nf++) {
            co[nf][0] *= sc0; co[nf][1] *= sc0;
            co[nf][2] *= sc1; co[nf][3] *= sc1;
        }

        // ---- write P (tf32, rna) to this warp's rows of QP buffer ----
        #pragma unroll
        for (int nf = 0; nf < 8; nf++) {
            int cbase = nf * 8 + 2 * t;
            sQP[(wm + g)     * QP_STR + cbase]     = __uint_as_float(f2tf(s[nf][0]));
            sQP[(wm + g)     * QP_STR + cbase + 1] = __uint_as_float(f2tf(s[nf][1]));
            sQP[(wm + g + 8) * QP_STR + cbase]     = __uint_as_float(f2tf(s[nf][2]));
            sQP[(wm + g + 8) * QP_STR + cbase + 1] = __uint_as_float(f2tf(s[nf][3]));
        }
        __syncwarp();

        // ---- O += P V ----
        #pragma unroll
        for (int ks = 0; ks < 8; ks++) {
            unsigned pa0 = __float_as_uint(sQP[(wm + g)     * QP_STR + ks * 8 + t]);
            unsigned pa1 = __float_as_uint(sQP[(wm + g + 8) * QP_STR + ks * 8 + t]);
            unsigned pa2 = __float_as_uint(sQP[(wm + g)     * QP_STR + ks * 8 + t + 4]);
            unsigned pa3 = __float_as_uint(sQP[(wm + g + 8) * QP_STR + ks * 8 + t + 4]);
            #pragma unroll
            for (int nf = 0; nf < 8; nf++) {
                unsigned b0 = __float_as_uint(sV[(ks * 8 + t)     * KV_STR + nf * 8 + g]);
                unsigned b1 = __float_as_uint(sV[(ks * 8 + t + 4) * KV_STR + nf * 8 + g]);
                mma_tf32(co[nf], pa0, pa1, pa2, pa3, b0, b1);
            }
        }
        __syncthreads();   // all warps done before next chunk overwrites sK/sV
    }

    // ---- epilogue ----
    float inv0 = 1.f / l0, inv1 = 1.f / l1;
    size_t row0 = (size_t)(b * SEQ + qrow0 + wm + g) * DMODEL + h * DH;
    size_t row1 = (size_t)(b * SEQ + qrow0 + wm + g + 8) * DMODEL + h * DH;
    #pragma unroll
    for (int nf = 0; nf < 8; nf++) {
        int cbase = nf * 8 + 2 * t;
        *(float2*)&O[row0 + cbase] = make_float2(co[nf][0] * inv0, co[nf][1] * inv0);
        *(float2*)&O[row1 + cbase] = make_float2(co[nf][2] * inv1, co[nf][3] * inv1);
    }
}

// ---------------- launch ----------------
extern "C" void kernel_launch(void* const* d_in, const int* in_sizes, int n_in,
                              void* d_out, int out_size)
{
    const float* x     = (const float*)d_in[0];
    const float* W_dq  = (const float*)d_in[1];
    const float* W_uq  = (const float*)d_in[2];
    const float* q_g   = (const float*)d_in[3];
    const float* q_b   = (const float*)d_in[4];
    const float* W_dkv = (const float*)d_in[5];
    const float* W_ukv = (const float*)d_in[6];
    const float* kv_g  = (const float*)d_in[7];
    const float* kv_b  = (const float*)d_in[8];
    const float* pq_g  = (const float*)d_in[9];
    const float* pq_b  = (const float*)d_in[10];
    const float* pk_g  = (const float*)d_in[11];
    const float* pk_b  = (const float*)d_in[12];
    const float* wo    = (const float*)d_in[13];
    float* out = (float*)d_out;

    float *xq, *xkv, *tq, *cq, *Qp, *tkv, *ckv, *KV, *attn, *woT;
    cudaGetSymbolAddress((void**)&xq,   g_xq);
    cudaGetSymbolAddress((void**)&xkv,  g_xkv);
    cudaGetSymbolAddress((void**)&tq,   g_tq);
    cudaGetSymbolAddress((void**)&cq,   g_cq);
    cudaGetSymbolAddress((void**)&Qp,   g_Q);
    cudaGetSymbolAddress((void**)&tkv,  g_tkv);
    cudaGetSymbolAddress((void**)&ckv,  g_ckv);
    cudaGetSymbolAddress((void**)&KV,   g_KV);
    cudaGetSymbolAddress((void**)&attn, g_attn);
    cudaGetSymbolAddress((void**)&woT,  g_woT);

    cudaFuncSetAttribute(attn_tc_kernel, cudaFuncAttributeMaxDynamicSharedMemorySize, ATT_SMEM);

    // 1. fused dual pre-LN (y=0) + wo transpose (y=1, independent work)
    prenorm_trans_kernel<<<dim3(MROWS, 2), 256>>>(
        x, pq_g, pq_b, pk_g, pk_b, xq, xkv, wo, woT);

    // 2. down-projections, batched (z-select): dq [4 x-tiles] + dkv [8 x-tiles]
    gemm_pair<false><<<dim3(KVPROJ / GBN, MROWS / GBM, 2), 256>>>(
        xq,  W_dq,  tq,  QPROJ,  DMODEL, 1.f, QPROJ / GBN,
        xkv, W_dkv, tkv, KVPROJ, DMODEL, 1.f, KVPROJ / GBN);

    // 3. the two inner LNs, batched
    ln_pair<<<dim3(MROWS, 2), 256>>>(
        tq,  q_g,  q_b,  cq,  QPROJ,
        tkv, kv_g, kv_b, ckv, KVPROJ);

    // 4. up-projections, batched (z-select): uq + ukv
    gemm_pair<true><<<dim3(2 * DMODEL / GBN, MROWS / GBM, 2), 256>>>(
        cq,  W_uq,  Qp, DMODEL,     QPROJ,  0.125f * LOG2E, DMODEL / GBN,
        ckv, W_ukv, KV, 2 * DMODEL, KVPROJ, 1.f,            2 * DMODEL / GBN);

    // 5. tensor-core causal flash attention (128-query tiles)
    attn_tc_kernel<<<dim3(SEQ / AQ_ROWS, NH, BATCH), 256, ATT_SMEM>>>(Qp, KV, attn);

    // 6. output projection via pre-transposed woT (conflict-free non-TB path)
    gemm_tf32<false><<<dim3(DMODEL / GBN, MROWS / GBM), 256>>>(attn, woT, out, DMODEL, DMODEL, 1.f);
}

// round 15
// speedup vs baseline: 1.1222x; 1.1222x over previous
#include <cuda_runtime.h>
#include <math.h>
#include <stdint.h>

#define MROWS 4096
#define DMODEL 1024
#define QPROJ 512
#define KVPROJ 1024
#define NH 16
#define DH 64
#define SEQ 2048
#define BATCH 2
#define EPS 1e-5f
#define LOG2E 1.44269504088896340736f

// ---------------- scratch (no allocations allowed) ----------------
__device__ float g_xq  [MROWS * DMODEL];
__device__ float g_xkv [MROWS * DMODEL];
__device__ float g_tq  [MROWS * QPROJ];
__device__ float g_cq  [MROWS * QPROJ];
__device__ float g_Q   [MROWS * DMODEL];
__device__ float g_tkv [MROWS * KVPROJ];
__device__ float g_ckv [MROWS * KVPROJ];
__device__ float g_KV  [MROWS * 2 * DMODEL];
__device__ float g_attn[MROWS * DMODEL];
__device__ float g_woT [DMODEL * DMODEL];   // wo transposed: woT[k][n] = wo[n][k]

// ---------------- tf32 helpers ----------------
__device__ __forceinline__ unsigned f2tf(float f) {
    unsigned u; asm("cvt.rna.tf32.f32 %0, %1;" : "=r"(u) : "f"(f)); return u;
}
__device__ __forceinline__ uint4 cvt4(float4 v) {
    uint4 u; u.x = f2tf(v.x); u.y = f2tf(v.y); u.z = f2tf(v.z); u.w = f2tf(v.w); return u;
}
__device__ __forceinline__ float ex2(float x) {
    float r; asm("ex2.approx.f32 %0, %1;" : "=f"(r) : "f"(x)); return r;
}
__device__ __forceinline__ void mma_tf32(float c[4], unsigned a0, unsigned a1, unsigned a2, unsigned a3,
                                         unsigned b0, unsigned b1) {
    asm volatile(
        "mma.sync.aligned.m16n8k8.row.col.f32.tf32.tf32.f32 "
        "{%0,%1,%2,%3},{%4,%5,%6,%7},{%8,%9},{%0,%1,%2,%3};"
        : "+f"(c[0]), "+f"(c[1]), "+f"(c[2]), "+f"(c[3])
        : "r"(a0), "r"(a1), "r"(a2), "r"(a3), "r"(b0), "r"(b1));
}

// ---------------- block reduction (sum, sumsq), 256 threads ----------------
__device__ __forceinline__ float2 block_reduce2(float s, float q, float* sh) {
    #pragma unroll
    for (int o = 16; o; o >>= 1) {
        s += __shfl_xor_sync(0xffffffffu, s, o);
        q += __shfl_xor_sync(0xffffffffu, q, o);
    }
    int w = threadIdx.x >> 5;
    if ((threadIdx.x & 31) == 0) { sh[w] = s; sh[8 + w] = q; }
    __syncthreads();
    if (threadIdx.x < 32) {
        s = (threadIdx.x < 8) ? sh[threadIdx.x] : 0.f;
        q = (threadIdx.x < 8) ? sh[8 + threadIdx.x] : 0.f;
        #pragma unroll
        for (int o = 4; o; o >>= 1) {
            s += __shfl_xor_sync(0xffffffffu, s, o);
            q += __shfl_xor_sync(0xffffffffu, q, o);
        }
        if (threadIdx.x == 0) { sh[16] = s; sh[17] = q; }
    }
    __syncthreads();
    return make_float2(sh[16], sh[17]);
}

// ---------------- fused dual pre-LN (y=0) + wo transpose (y=1) --------------
__global__ void __launch_bounds__(256) prenorm_trans_kernel(
    const float* __restrict__ x,
    const float* __restrict__ pg, const float* __restrict__ pb,
    const float* __restrict__ kg, const float* __restrict__ kb,
    float* __restrict__ xq, float* __restrict__ xkv,
    const float* __restrict__ wo, float* __restrict__ woT)
{
    __shared__ float sh[32 * 33];
    if (blockIdx.y == 1) {
        int idx = blockIdx.x;
        if (idx >= (DMODEL / 32) * (DMODEL / 32)) return;
        int i0 = (idx & (DMODEL / 32 - 1)) * 32;   // k block
        int j0 = (idx / (DMODEL / 32)) * 32;       // n block
        int tx = threadIdx.x & 31, ty = threadIdx.x >> 5;
        #pragma unroll
        for (int j = 0; j < 4; j++)
            sh[(ty + j * 8) * 33 + tx] = wo[(size_t)(j0 + ty + j * 8) * DMODEL + i0 + tx];
        __syncthreads();
        #pragma unroll
        for (int j = 0; j < 4; j++)
            woT[(size_t)(i0 + ty + j * 8) * DMODEL + j0 + tx] = sh[tx * 33 + ty + j * 8];
        return;
    }
    int row = blockIdx.x;
    int i = threadIdx.x * 4;
    const float* xr = x + (size_t)row * DMODEL;
    float4 v = *(const float4*)&xr[i];
    float s = v.x + v.y + v.z + v.w;
    float q = v.x * v.x + v.y * v.y + v.z * v.z + v.w * v.w;
    float2 r = block_reduce2(s, q, sh);
    float mu = r.x * (1.f / DMODEL);
    float var = r.y * (1.f / DMODEL) - mu * mu;
    float inv = rsqrtf(var + EPS);
    float4 g1 = *(const float4*)&pg[i], b1 = *(const float4*)&pb[i];
    float4 g2 = *(const float4*)&kg[i], b2 = *(const float4*)&kb[i];
    float4 n = make_float4((v.x - mu) * inv, (v.y - mu) * inv, (v.z - mu) * inv, (v.w - mu) * inv);
    *(float4*)&xq [(size_t)row * DMODEL + i] =
        make_float4(n.x * g1.x + b1.x, n.y * g1.y + b1.y, n.z * g1.z + b1.z, n.w * g1.w + b1.w);
    *(float4*)&xkv[(size_t)row * DMODEL + i] =
        make_float4(n.x * g2.x + b2.x, n.y * g2.y + b2.y, n.z * g2.z + b2.z, n.w * g2.w + b2.w);
}

// ---------------- row LN core + batched pair --------------------------------
__device__ __forceinline__ void ln_core(
    const float* __restrict__ x, const float* __restrict__ g,
    const float* __restrict__ b, float* __restrict__ y, int N, float* sh)
{
    int row = blockIdx.x;
    const float* xr = x + (size_t)row * N;
    float s = 0.f, q = 0.f;
    for (int i = threadIdx.x * 4; i < N; i += 1024) {
        float4 v = *(const float4*)&xr[i];
        s += v.x + v.y + v.z + v.w;
        q += v.x * v.x + v.y * v.y + v.z * v.z + v.w * v.w;
    }
    float2 r = block_reduce2(s, q, sh);
    float mu = r.x / N;
    float var = r.y / N - mu * mu;
    float inv = rsqrtf(var + EPS);
    for (int i = threadIdx.x * 4; i < N; i += 1024) {
        float4 v = *(const float4*)&xr[i];
        float4 gv = *(const float4*)&g[i], bv = *(const float4*)&b[i];
        *(float4*)&y[(size_t)row * N + i] = make_float4(
            (v.x - mu) * inv * gv.x + bv.x, (v.y - mu) * inv * gv.y + bv.y,
            (v.z - mu) * inv * gv.z + bv.z, (v.w - mu) * inv * gv.w + bv.w);
    }
}

__global__ void __launch_bounds__(256) ln_pair(
    const float* __restrict__ x0, const float* __restrict__ g0,
    const float* __restrict__ b0, float* __restrict__ y0, int N0,
    const float* __restrict__ x1, const float* __restrict__ g1,
    const float* __restrict__ b1, float* __restrict__ y1, int N1)
{
    __shared__ float sh[18];
    if (blockIdx.y == 0) ln_core(x0, g0, b0, y0, N0, sh);
    else                 ln_core(x1, g1, b1, y1, N1, sh);
}

// ---------------- tf32 tensor-core GEMM core (R5 body) ----------------------
#define GBM 128
#define GBN 128
#define GBK 32
#define ASTRIDE 516
#define BSTRIDE 136

template <bool ROUND>
__device__ __forceinline__ void gemm_core(
    unsigned* As, unsigned* Bs,
    const float* __restrict__ A, const float* __restrict__ B,
    float* __restrict__ C, int N, int K, float alpha)
{
    int tid = threadIdx.x;
    int m0 = blockIdx.y * GBM, n0 = blockIdx.x * GBN;
    int warp = tid >> 5, lane = tid & 31;
    int g = lane >> 2, t = lane & 3;
    int wm = (warp & 1) * 64, wn = (warp >> 1) * 32;

    int ar = tid >> 3, ac4 = tid & 7;
    int br = tid >> 5, bc4 = tid & 31;

    float4 ra[4], rb[4];

    auto loadT = [&](int k0) {
        #pragma unroll
        for (int i = 0; i < 4; i++)
            ra[i] = *(const float4*)&A[(size_t)(m0 + ar + 32 * i) * K + k0 + ac4 * 4];
        #pragma unroll
        for (int i = 0; i < 4; i++)
            rb[i] = *(const float4*)&B[(size_t)(k0 + br + 8 * i) * N + n0 + bc4 * 4];
    };
    auto storeT = [&]() {
        #pragma unroll
        for (int i = 0; i < 4; i++)
            *(uint4*)&As[ac4 * ASTRIDE + (ar + 32 * i) * 4] = cvt4(ra[i]);
        #pragma unroll
        for (int i = 0; i < 4; i++)
            *(uint4*)&Bs[(br + 8 * i) * BSTRIDE + bc4 * 4] = cvt4(rb[i]);
    };

    float c[4][4][4] = {};

    loadT(0);
    storeT();
    __syncthreads();

    for (int k0 = GBK; ; k0 += GBK) {
        bool more = k0 < K;
        if (more) loadT(k0);

        #pragma unroll
        for (int ks = 0; ks < GBK; ks += 8) {
            unsigned bf[4][2];
            #pragma unroll
            for (int nf = 0; nf < 4; nf++) {
                bf[nf][0] = Bs[(ks + t) * BSTRIDE + wn + nf * 8 + g];
                bf[nf][1] = Bs[(ks + t + 4) * BSTRIDE + wn + nf * 8 + g];
            }
            #pragma unroll
            for (int mf = 0; mf < 4; mf++) {
                int mb = wm + mf * 16 + g;
                int grp = ks >> 2;
                unsigned a0 = As[grp * ASTRIDE + mb * 4 + t];
                unsigned a1 = As[grp * ASTRIDE + (mb + 8) * 4 + t];
                unsigned a2 = As[(grp + 1) * ASTRIDE + mb * 4 + t];
                unsigned a3 = As[(grp + 1) * ASTRIDE + (mb + 8) * 4 + t];
                #pragma unroll
                for (int nf = 0; nf < 4; nf++)
                    mma_tf32(c[mf][nf], a0, a1, a2, a3, bf[nf][0], bf[nf][1]);
            }
        }
        if (!more) break;
        __syncthreads();
        storeT();
        __syncthreads();
    }

    auto outv = [&](float v) -> float {
        return ROUND ? __uint_as_float(f2tf(alpha * v)) : alpha * v;
    };
    #pragma unroll
    for (int mf = 0; mf < 4; mf++) {
        int r0 = m0 + wm + mf * 16 + g;
        #pragma unroll
        for (int nf = 0; nf < 4; nf++) {
            int cc = n0 + wn + nf * 8 + 2 * t;
            float2 lo = make_float2(outv(c[mf][nf][0]), outv(c[mf][nf][1]));
            float2 hi = make_float2(outv(c[mf][nf][2]), outv(c[mf][nf][3]));
            *(float2*)&C[(size_t)r0 * N + cc] = lo;
            *(float2*)&C[(size_t)(r0 + 8) * N + cc] = hi;
        }
    }
}

// solo gemm (wo, via pre-transposed woT -> non-TB path)
template <bool ROUND>
__global__ void __launch_bounds__(256) gemm_tf32(
    const float* __restrict__ A, const float* __restrict__ B,
    float* __restrict__ C, int N, int K, float alpha)
{
    __shared__ unsigned As[8 * ASTRIDE];
    __shared__ unsigned Bs[GBK * BSTRIDE];
    gemm_core<ROUND>(As, Bs, A, B, C, N, K, alpha);
}

// batched pair of independent GEMMs: blockIdx.z selects. Inactive x-tiles exit.
template <bool ROUND>
__global__ void __launch_bounds__(256, 2) gemm_pair(
    const float* __restrict__ A0, const float* __restrict__ B0, float* __restrict__ C0,
    int N0, int K0, float al0, int nx0,
    const float* __restrict__ A1, const float* __restrict__ B1, float* __restrict__ C1,
    int N1, int K1, float al1, int nx1)
{
    __shared__ unsigned As[8 * ASTRIDE];
    __shared__ unsigned Bs[GBK * BSTRIDE];
    if (blockIdx.z == 0) {
        if ((int)blockIdx.x >= nx0) return;
        gemm_core<ROUND>(As, Bs, A0, B0, C0, N0, K0, al0);
    } else {
        if ((int)blockIdx.x >= nx1) return;
        gemm_core<ROUND>(As, Bs, A1, B1, C1, N1, K1, al1);
    }
}

// ---------------- tensor-core causal flash attention (R13 core) --------------
// Grid: x = h*BATCH + b (fast), y = qt index with heavy tiles first (slow) —
// longest-job-first: all qt=31 blocks launch before any qt=30 block, etc.
#define QP_STR 68
#define KV_STR 76
#define ATT_SMEM ((64 * QP_STR + 2 * 64 * KV_STR) * 4)

extern __shared__ float att_sm[];

__global__ void __launch_bounds__(128) attn_tc_kernel(
    const float* __restrict__ Q, const float* __restrict__ KV, float* __restrict__ O)
{
    float* sQP = att_sm;
    float* sK  = sQP + 64 * QP_STR;
    float* sV  = sK  + 64 * KV_STR;

    int tid = threadIdx.x, warp = tid >> 5, lane = tid & 31;
    int g = lane >> 2, t = lane & 3;
    int wm = warp * 16;
    int hb = blockIdx.x;
    int h = hb >> 1, b = hb & 1;
    int qt = (int)gridDim.y - 1 - (int)blockIdx.y;   // heavy (large qt) first
    int qrow0 = qt * 64;

    #pragma unroll
    for (int it = 0; it < 8; it++) {
        int idx = tid + it * 128;
        int r = idx >> 4, c4 = idx & 15;
        float4 v = *(const float4*)&Q[((size_t)(b * SEQ + qrow0 + r)) * DMODEL + h * DH + c4 * 4];
        *(float4*)&sQP[r * QP_STR + c4 * 4] = v;
    }
    __syncthreads();

    unsigned qa[8][4];
    #pragma unroll
    for (int ks = 0; ks < 8; ks++) {
        qa[ks][0] = __float_as_uint(sQP[(wm + g)     * QP_STR + ks * 8 + t]);
        qa[ks][1] = __float_as_uint(sQP[(wm + g + 8) * QP_STR + ks * 8 + t]);
        qa[ks][2] = __float_as_uint(sQP[(wm + g)     * QP_STR + ks * 8 + t + 4]);
        qa[ks][3] = __float_as_uint(sQP[(wm + g + 8) * QP_STR + ks * 8 + t + 4]);
    }
    __syncthreads();

    float m0 = -INFINITY, m1 = -INFINITY, l0 = 0.f, l1 = 0.f;
    float co[8][4] = {};

    for (int ch = 0; ch <= qt; ch++) {
        #pragma unroll
        for (int it = 0; it < 8; it++) {
            int idx = tid + it * 128;
            int r = idx >> 4, c4 = idx & 15;
            size_t base = ((size_t)(b * SEQ + ch * 64 + r)) * (2 * DMODEL) + h * DH + c4 * 4;
            float4 k4 = *(const float4*)&KV[base];
            float4 v4 = *(const float4*)&KV[base + DMODEL];
            *(float4*)&sK[r * KV_STR + c4 * 4] = k4;
            *(float4*)&sV[r * KV_STR + c4 * 4] = v4;
        }
        __syncthreads();

        float s[8][4] = {};
        #pragma unroll
        for (int ks = 0; ks < 8; ks++) {
            #pragma unroll
            for (int nf = 0; nf < 8; nf++) {
                unsigned b0 = __float_as_uint(sK[(nf * 8 + g) * KV_STR + ks * 8 + t]);
                unsigned b1 = __float_as_uint(sK[(nf * 8 + g) * KV_STR + ks * 8 + t + 4]);
                mma_tf32(s[nf], qa[ks][0], qa[ks][1], qa[ks][2], qa[ks][3], b0, b1);
            }
        }

        if (ch == qt) {
            int r0 = wm + g, r1 = wm + g + 8;
            #pragma unroll
            for (int nf = 0; nf < 8; nf++) {
                int col = nf * 8 + 2 * t;
                if (col     > r0) s[nf][0] = -1e30f;
                if (col + 1 > r0) s[nf][1] = -1e30f;
                if (col     > r1) s[nf][2] = -1e30f;
                if (col + 1 > r1) s[nf][3] = -1e30f;
            }
        }

        float mx0 = -1e30f, mx1 = -1e30f;
        #pragma unroll
        for (int nf = 0; nf < 8; nf++) {
            mx0 = fmaxf(mx0, fmaxf(s[nf][0], s[nf][1]));
            mx1 = fmaxf(mx1, fmaxf(s[nf][2], s[nf][3]));
        }
        mx0 = fmaxf(mx0, __shfl_xor_sync(0xffffffffu, mx0, 1));
        mx0 = fmaxf(mx0, __shfl_xor_sync(0xffffffffu, mx0, 2));
        mx1 = fmaxf(mx1, __shfl_xor_sync(0xffffffffu, mx1, 1));
        mx1 = fmaxf(mx1, __shfl_xor_sync(0xffffffffu, mx1, 2));
        float nm0 = fmaxf(m0, mx0), nm1 = fmaxf(m1, mx1);
        float sc0 = ex2(m0 - nm0), sc1 = ex2(m1 - nm1);
        m0 = nm0; m1 = nm1;
        float sum0 = 0.f, sum1 = 0.f;
        #pragma unroll
        for (int nf = 0; nf < 8; nf++) {
            s[nf][0] = ex2(s[nf][0] - m0); sum0 += s[nf][0];
            s[nf][1] = ex2(s[nf][1] - m0); sum0 += s[nf][1];
            s[nf][2] = ex2(s[nf][2] - m1); sum1 += s[nf][2];
            s[nf][3] = ex2(s[nf][3] - m1); sum1 += s[nf][3];
        }
        sum0 += __shfl_xor_sync(0xffffffffu, sum0, 1);
        sum0 += __shfl_xor_sync(0xffffffffu, sum0, 2);
        sum1 += __shfl_xor_sync(0xffffffffu, sum1, 1);
        sum1 += __shfl_xor_sync(0xffffffffu, sum1, 2);
        l0 = l0 * sc0 + sum0;
        l1 = l1 * sc1 + sum1;
        #pragma unroll
        for (int nf = 0; nf < 8; nf++) {
            co[nf][0] *= sc0; co[nf][1] *= sc0;
            co[nf][2] *= sc1; co[nf][3] *= sc1;
        }

        #pragma unroll
        for (int nf = 0; nf < 8; nf++) {
            int cbase = nf * 8 + 2 * t;
            sQP[(wm + g)     * QP_STR + cbase]     = __uint_as_float(f2tf(s[nf][0]));
            sQP[(wm + g)     * QP_STR + cbase + 1] = __uint_as_float(f2tf(s[nf][1]));
            sQP[(wm + g + 8) * QP_STR + cbase]     = __uint_as_float(f2tf(s[nf][2]));
            sQP[(wm + g + 8) * QP_STR + cbase + 1] = __uint_as_float(f2tf(s[nf][3]));
        }
        __syncwarp();

        #pragma unroll
        for (int ks = 0; ks < 8; ks++) {
            unsigned pa0 = __float_as_uint(sQP[(wm + g)     * QP_STR + ks * 8 + t]);
            unsigned pa1 = __float_as_uint(sQP[(wm + g + 8) * QP_STR + ks * 8 + t]);
            unsigned pa2 = __float_as_uint(sQP[(wm + g)     * QP_STR + ks * 8 + t + 4]);
            unsigned pa3 = __float_as_uint(sQP[(wm + g + 8) * QP_STR + ks * 8 + t + 4]);
            #pragma unroll
            for (int nf = 0; nf < 8; nf++) {
                unsigned b0 = __float_as_uint(sV[(ks * 8 + t)     * KV_STR + nf * 8 + g]);
                unsigned b1 = __float_as_uint(sV[(ks * 8 + t + 4) * KV_STR + nf * 8 + g]);
                mma_tf32(co[nf], pa0, pa1, pa2, pa3, b0, b1);
            }
        }
        __syncthreads();
    }

    float inv0 = 1.f / l0, inv1 = 1.f / l1;
    size_t row0 = (size_t)(b * SEQ + qrow0 + wm + g) * DMODEL + h * DH;
    size_t row1 = (size_t)(b * SEQ + qrow0 + wm + g + 8) * DMODEL + h * DH;
    #pragma unroll
    for (int nf = 0; nf < 8; nf++) {
        int cbase = nf * 8 + 2 * t;
        *(float2*)&O[row0 + cbase] = make_float2(co[nf][0] * inv0, co[nf][1] * inv0);
        *(float2*)&O[row1 + cbase] = make_float2(co[nf][2] * inv1, co[nf][3] * inv1);
    }
}

// ---------------- launch ----------------
extern "C" void kernel_launch(void* const* d_in, const int* in_sizes, int n_in,
                              void* d_out, int out_size)
{
    const float* x     = (const float*)d_in[0];
    const float* W_dq  = (const float*)d_in[1];
    const float* W_uq  = (const float*)d_in[2];
    const float* q_g   = (const float*)d_in[3];
    const float* q_b   = (const float*)d_in[4];
    const float* W_dkv = (const float*)d_in[5];
    const float* W_ukv = (const float*)d_in[6];
    const float* kv_g  = (const float*)d_in[7];
    const float* kv_b  = (const float*)d_in[8];
    const float* pq_g  = (const float*)d_in[9];
    const float* pq_b  = (const float*)d_in[10];
    const float* pk_g  = (const float*)d_in[11];
    const float* pk_b  = (const float*)d_in[12];
    const float* wo    = (const float*)d_in[13];
    float* out = (float*)d_out;

    float *xq, *xkv, *tq, *cq, *Qp, *tkv, *ckv, *KV, *attn, *woT;
    cudaGetSymbolAddress((void**)&xq,   g_xq);
    cudaGetSymbolAddress((void**)&xkv,  g_xkv);
    cudaGetSymbolAddress((void**)&tq,   g_tq);
    cudaGetSymbolAddress((void**)&cq,   g_cq);
    cudaGetSymbolAddress((void**)&Qp,   g_Q);
    cudaGetSymbolAddress((void**)&tkv,  g_tkv);
    cudaGetSymbolAddress((void**)&ckv,  g_ckv);
    cudaGetSymbolAddress((void**)&KV,   g_KV);
    cudaGetSymbolAddress((void**)&attn, g_attn);
    cudaGetSymbolAddress((void**)&woT,  g_woT);

    cudaFuncSetAttribute(attn_tc_kernel, cudaFuncAttributeMaxDynamicSharedMemorySize, ATT_SMEM);

    // 1. fused dual pre-LN (y=0) + wo transpose (y=1, independent work)
    prenorm_trans_kernel<<<dim3(MROWS, 2), 256>>>(
        x, pq_g, pq_b, pk_g, pk_b, xq, xkv, wo, woT);

    // 2. down-projections, batched (z-select): dq [4 x-tiles] + dkv [8 x-tiles]
    gemm_pair<false><<<dim3(KVPROJ / GBN, MROWS / GBM, 2), 256>>>(
        xq,  W_dq,  tq,  QPROJ,  DMODEL, 1.f, QPROJ / GBN,
        xkv, W_dkv, tkv, KVPROJ, DMODEL, 1.f, KVPROJ / GBN);

    // 3. the two inner LNs, batched
    ln_pair<<<dim3(MROWS, 2), 256>>>(
        tq,  q_g,  q_b,  cq,  QPROJ,
        tkv, kv_g, kv_b, ckv, KVPROJ);

    // 4. up-projections, batched (z-select): uq + ukv
    gemm_pair<true><<<dim3(2 * DMODEL / GBN, MROWS / GBM, 2), 256>>>(
        cq,  W_uq,  Qp, DMODEL,     QPROJ,  0.125f * LOG2E, DMODEL / GBN,
        ckv, W_ukv, KV, 2 * DMODEL, KVPROJ, 1.f,            2 * DMODEL / GBN);

    // 5. attention: longest-job-first grid (x = h,b fast; y = qt heavy-first)
    attn_tc_kernel<<<dim3(NH * BATCH, SEQ / 64), 128, ATT_SMEM>>>(Qp, KV, attn);

    // 6. output projection via pre-transposed woT (conflict-free non-TB path)
    gemm_tf32<false><<<dim3(DMODEL / GBN, MROWS / GBM), 256>>>(attn, woT, out, DMODEL, DMODEL, 1.f);
}

// round 16
// speedup vs baseline: 1.1437x; 1.0192x over previous
#include <cuda_runtime.h>
#include <math.h>
#include <stdint.h>

#define MROWS 4096
#define DMODEL 1024
#define QPROJ 512
#define KVPROJ 1024
#define NH 16
#define DH 64
#define SEQ 2048
#define BATCH 2
#define EPS 1e-5f
#define LOG2E 1.44269504088896340736f

// ---------------- scratch (no allocations allowed) ----------------
__device__ float g_xq  [MROWS * DMODEL];
__device__ float g_xkv [MROWS * DMODEL];
__device__ float g_tq  [MROWS * QPROJ];
__device__ float g_cq  [MROWS * QPROJ];
__device__ float g_Q   [MROWS * DMODEL];
__device__ float g_tkv [MROWS * KVPROJ];
__device__ float g_ckv [MROWS * KVPROJ];
__device__ float g_KV  [MROWS * 2 * DMODEL];
__device__ float g_attn[MROWS * DMODEL];
__device__ float g_woT [DMODEL * DMODEL];   // wo transposed: woT[k][n] = wo[n][k]

// ---------------- tf32 helpers ----------------
__device__ __forceinline__ unsigned f2tf(float f) {
    unsigned u; asm("cvt.rna.tf32.f32 %0, %1;" : "=r"(u) : "f"(f)); return u;
}
__device__ __forceinline__ uint4 cvt4(float4 v) {
    uint4 u; u.x = f2tf(v.x); u.y = f2tf(v.y); u.z = f2tf(v.z); u.w = f2tf(v.w); return u;
}
__device__ __forceinline__ float ex2(float x) {
    float r; asm("ex2.approx.f32 %0, %1;" : "=f"(r) : "f"(x)); return r;
}
__device__ __forceinline__ void mma_tf32(float c[4], unsigned a0, unsigned a1, unsigned a2, unsigned a3,
                                         unsigned b0, unsigned b1) {
    asm volatile(
        "mma.sync.aligned.m16n8k8.row.col.f32.tf32.tf32.f32 "
        "{%0,%1,%2,%3},{%4,%5,%6,%7},{%8,%9},{%0,%1,%2,%3};"
        : "+f"(c[0]), "+f"(c[1]), "+f"(c[2]), "+f"(c[3])
        : "r"(a0), "r"(a1), "r"(a2), "r"(a3), "r"(b0), "r"(b1));
}
__device__ __forceinline__ void ldsm4(unsigned& r0, unsigned& r1, unsigned& r2, unsigned& r3,
                                      uint32_t addr) {
    asm volatile("ldmatrix.sync.aligned.m8n8.x4.shared.b16 {%0,%1,%2,%3}, [%4];"
        : "=r"(r0), "=r"(r1), "=r"(r2), "=r"(r3) : "r"(addr));
}
__device__ __forceinline__ uint32_t smem_u32(const void* p) {
    uint32_t a;
    asm("{ .reg .u64 t; cvta.to.shared.u64 t, %1; cvt.u32.u64 %0, t; }" : "=r"(a) : "l"(p));
    return a;
}

// ---------------- block reduction (sum, sumsq), 256 threads ----------------
__device__ __forceinline__ float2 block_reduce2(float s, float q, float* sh) {
    #pragma unroll
    for (int o = 16; o; o >>= 1) {
        s += __shfl_xor_sync(0xffffffffu, s, o);
        q += __shfl_xor_sync(0xffffffffu, q, o);
    }
    int w = threadIdx.x >> 5;
    if ((threadIdx.x & 31) == 0) { sh[w] = s; sh[8 + w] = q; }
    __syncthreads();
    if (threadIdx.x < 32) {
        s = (threadIdx.x < 8) ? sh[threadIdx.x] : 0.f;
        q = (threadIdx.x < 8) ? sh[8 + threadIdx.x] : 0.f;
        #pragma unroll
        for (int o = 4; o; o >>= 1) {
            s += __shfl_xor_sync(0xffffffffu, s, o);
            q += __shfl_xor_sync(0xffffffffu, q, o);
        }
        if (threadIdx.x == 0) { sh[16] = s; sh[17] = q; }
    }
    __syncthreads();
    return make_float2(sh[16], sh[17]);
}

// ---------------- fused dual pre-LN (y=0) + wo transpose (y=1) --------------
__global__ void __launch_bounds__(256) prenorm_trans_kernel(
    const float* __restrict__ x,
    const float* __restrict__ pg, const float* __restrict__ pb,
    const float* __restrict__ kg, const float* __restrict__ kb,
    float* __restrict__ xq, float* __restrict__ xkv,
    const float* __restrict__ wo, float* __restrict__ woT)
{
    __shared__ float sh[32 * 33];
    if (blockIdx.y == 1) {
        int idx = blockIdx.x;
        if (idx >= (DMODEL / 32) * (DMODEL / 32)) return;
        int i0 = (idx & (DMODEL / 32 - 1)) * 32;   // k block
        int j0 = (idx / (DMODEL / 32)) * 32;       // n block
        int tx = threadIdx.x & 31, ty = threadIdx.x >> 5;
        #pragma unroll
        for (int j = 0; j < 4; j++)
            sh[(ty + j * 8) * 33 + tx] = wo[(size_t)(j0 + ty + j * 8) * DMODEL + i0 + tx];
        __syncthreads();
        #pragma unroll
        for (int j = 0; j < 4; j++)
            woT[(size_t)(i0 + ty + j * 8) * DMODEL + j0 + tx] = sh[tx * 33 + ty + j * 8];
        return;
    }
    int row = blockIdx.x;
    int i = threadIdx.x * 4;
    const float* xr = x + (size_t)row * DMODEL;
    float4 v = *(const float4*)&xr[i];
    float s = v.x + v.y + v.z + v.w;
    float q = v.x * v.x + v.y * v.y + v.z * v.z + v.w * v.w;
    float2 r = block_reduce2(s, q, sh);
    float mu = r.x * (1.f / DMODEL);
    float var = r.y * (1.f / DMODEL) - mu * mu;
    float inv = rsqrtf(var + EPS);
    float4 g1 = *(const float4*)&pg[i], b1 = *(const float4*)&pb[i];
    float4 g2 = *(const float4*)&kg[i], b2 = *(const float4*)&kb[i];
    float4 n = make_float4((v.x - mu) * inv, (v.y - mu) * inv, (v.z - mu) * inv, (v.w - mu) * inv);
    *(float4*)&xq [(size_t)row * DMODEL + i] =
        make_float4(n.x * g1.x + b1.x, n.y * g1.y + b1.y, n.z * g1.z + b1.z, n.w * g1.w + b1.w);
    *(float4*)&xkv[(size_t)row * DMODEL + i] =
        make_float4(n.x * g2.x + b2.x, n.y * g2.y + b2.y, n.z * g2.z + b2.z, n.w * g2.w + b2.w);
}

// ---------------- row LN core + batched pair --------------------------------
__device__ __forceinline__ void ln_core(
    const float* __restrict__ x, const float* __restrict__ g,
    const float* __restrict__ b, float* __restrict__ y, int N, float* sh)
{
    int row = blockIdx.x;
    const float* xr = x + (size_t)row * N;
    float s = 0.f, q = 0.f;
    for (int i = threadIdx.x * 4; i < N; i += 1024) {
        float4 v = *(const float4*)&xr[i];
        s += v.x + v.y + v.z + v.w;
        q += v.x * v.x + v.y * v.y + v.z * v.z + v.w * v.w;
    }
    float2 r = block_reduce2(s, q, sh);
    float mu = r.x / N;
    float var = r.y / N - mu * mu;
    float inv = rsqrtf(var + EPS);
    for (int i = threadIdx.x * 4; i < N; i += 1024) {
        float4 v = *(const float4*)&xr[i];
        float4 gv = *(const float4*)&g[i], bv = *(const float4*)&b[i];
        *(float4*)&y[(size_t)row * N + i] = make_float4(
            (v.x - mu) * inv * gv.x + bv.x, (v.y - mu) * inv * gv.y + bv.y,
            (v.z - mu) * inv * gv.z + bv.z, (v.w - mu) * inv * gv.w + bv.w);
    }
}

__global__ void __launch_bounds__(256) ln_pair(
    const float* __restrict__ x0, const float* __restrict__ g0,
    const float* __restrict__ b0, float* __restrict__ y0, int N0,
    const float* __restrict__ x1, const float* __restrict__ g1,
    const float* __restrict__ b1, float* __restrict__ y1, int N1)
{
    __shared__ float sh[18];
    if (blockIdx.y == 0) ln_core(x0, g0, b0, y0, N0, sh);
    else                 ln_core(x1, g1, b1, y1, N1, sh);
}

// ---------------- tf32 tensor-core GEMM core ---------------------------------
// R5 single-buffer structure; A-fragments via ldmatrix.x4 (R9-validated lane
// mapping on the same k-group-major ASTRIDE-516 layout). B frags scalar LDS.
#define GBM 128
#define GBN 128
#define GBK 32
#define ASTRIDE 516
#define BSTRIDE 136

template <bool ROUND>
__device__ __forceinline__ void gemm_core(
    unsigned* As, unsigned* Bs,
    const float* __restrict__ A, const float* __restrict__ B,
    float* __restrict__ C, int N, int K, float alpha)
{
    int tid = threadIdx.x;
    int m0 = blockIdx.y * GBM, n0 = blockIdx.x * GBN;
    int warp = tid >> 5, lane = tid & 31;
    int g = lane >> 2, t = lane & 3;
    int wm = (warp & 1) * 64, wn = (warp >> 1) * 32;

    int ar = tid >> 3, ac4 = tid & 7;
    int br = tid >> 5, bc4 = tid & 31;

    // ldmatrix per-lane base (bytes from As): lanes 0-7 rows 0-7 of (grp),
    // 8-15 rows 8-15 of (grp), 16-31 the same rows at (grp+1).
    int row_off = ((lane >> 3) & 1) * 8 + (lane & 7);
    uint32_t abase = smem_u32(As)
                   + (uint32_t)((lane >> 4) * (ASTRIDE * 4) + (wm + row_off) * 16);

    float4 ra[4], rb[4];

    auto loadT = [&](int k0) {
        #pragma unroll
        for (int i = 0; i < 4; i++)
            ra[i] = *(const float4*)&A[(size_t)(m0 + ar + 32 * i) * K + k0 + ac4 * 4];
        #pragma unroll
        for (int i = 0; i < 4; i++)
            rb[i] = *(const float4*)&B[(size_t)(k0 + br + 8 * i) * N + n0 + bc4 * 4];
    };
    auto storeT = [&]() {
        #pragma unroll
        for (int i = 0; i < 4; i++)
            *(uint4*)&As[ac4 * ASTRIDE + (ar + 32 * i) * 4] = cvt4(ra[i]);
        #pragma unroll
        for (int i = 0; i < 4; i++)
            *(uint4*)&Bs[(br + 8 * i) * BSTRIDE + bc4 * 4] = cvt4(rb[i]);
    };

    float c[4][4][4] = {};

    loadT(0);
    storeT();
    __syncthreads();

    for (int k0 = GBK; ; k0 += GBK) {
        bool more = k0 < K;
        if (more) loadT(k0);

        #pragma unroll
        for (int ks = 0; ks < GBK; ks += 8) {
            unsigned bf[4][2];
            #pragma unroll
            for (int nf = 0; nf < 4; nf++) {
                bf[nf][0] = Bs[(ks + t) * BSTRIDE + wn + nf * 8 + g];
                bf[nf][1] = Bs[(ks + t + 4) * BSTRIDE + wn + nf * 8 + g];
            }
            #pragma unroll
            for (int mf = 0; mf < 4; mf++) {
                unsigned a0, a1, a2, a3;
                ldsm4(a0, a1, a2, a3,
                      abase + (uint32_t)mf * 256 + (uint32_t)(ks >> 2) * (ASTRIDE * 4));
                #pragma unroll
                for (int nf = 0; nf < 4; nf++)
                    mma_tf32(c[mf][nf], a0, a1, a2, a3, bf[nf][0], bf[nf][1]);
            }
        }
        if (!more) break;
        __syncthreads();
        storeT();
        __syncthreads();
    }

    auto outv = [&](float v) -> float {
        return ROUND ? __uint_as_float(f2tf(alpha * v)) : alpha * v;
    };
    #pragma unroll
    for (int mf = 0; mf < 4; mf++) {
        int r0 = m0 + wm + mf * 16 + g;
        #pragma unroll
        for (int nf = 0; nf < 4; nf++) {
            int cc = n0 + wn + nf * 8 + 2 * t;
            float2 lo = make_float2(outv(c[mf][nf][0]), outv(c[mf][nf][1]));
            float2 hi = make_float2(outv(c[mf][nf][2]), outv(c[mf][nf][3]));
            *(float2*)&C[(size_t)r0 * N + cc] = lo;
            *(float2*)&C[(size_t)(r0 + 8) * N + cc] = hi;
        }
    }
}

// solo gemm (wo, via pre-transposed woT -> non-TB path)
template <bool ROUND>
__global__ void __launch_bounds__(256, 2) gemm_tf32(
    const float* __restrict__ A, const float* __restrict__ B,
    float* __restrict__ C, int N, int K, float alpha)
{
    __shared__ unsigned As[8 * ASTRIDE];
    __shared__ unsigned Bs[GBK * BSTRIDE];
    gemm_core<ROUND>(As, Bs, A, B, C, N, K, alpha);
}

// batched pair of independent GEMMs: blockIdx.z selects. Inactive x-tiles exit.
template <bool ROUND>
__global__ void __launch_bounds__(256, 2) gemm_pair(
    const float* __restrict__ A0, const float* __restrict__ B0, float* __restrict__ C0,
    int N0, int K0, float al0, int nx0,
    const float* __restrict__ A1, const float* __restrict__ B1, float* __restrict__ C1,
    int N1, int K1, float al1, int nx1)
{
    __shared__ unsigned As[8 * ASTRIDE];
    __shared__ unsigned Bs[GBK * BSTRIDE];
    if (blockIdx.z == 0) {
        if ((int)blockIdx.x >= nx0) return;
        gemm_core<ROUND>(As, Bs, A0, B0, C0, N0, K0, al0);
    } else {
        if ((int)blockIdx.x >= nx1) return;
        gemm_core<ROUND>(As, Bs, A1, B1, C1, N1, K1, al1);
    }
}

// ---------------- tensor-core causal flash attention (R15, verbatim) ---------
// Grid: x = h*BATCH + b (fast), y = qt with heavy tiles first (slow) — LJF.
#define QP_STR 68
#define KV_STR 76
#define ATT_SMEM ((64 * QP_STR + 2 * 64 * KV_STR) * 4)

extern __shared__ float att_sm[];

__global__ void __launch_bounds__(128) attn_tc_kernel(
    const float* __restrict__ Q, const float* __restrict__ KV, float* __restrict__ O)
{
    float* sQP = att_sm;
    float* sK  = sQP + 64 * QP_STR;
    float* sV  = sK  + 64 * KV_STR;

    int tid = threadIdx.x, warp = tid >> 5, lane = tid & 31;
    int g = lane >> 2, t = lane & 3;
    int wm = warp * 16;
    int hb = blockIdx.x;
    int h = hb >> 1, b = hb & 1;
    int qt = (int)gridDim.y - 1 - (int)blockIdx.y;   // heavy (large qt) first
    int qrow0 = qt * 64;

    #pragma unroll
    for (int it = 0; it < 8; it++) {
        int idx = tid + it * 128;
        int r = idx >> 4, c4 = idx & 15;
        float4 v = *(const float4*)&Q[((size_t)(b * SEQ + qrow0 + r)) * DMODEL + h * DH + c4 * 4];
        *(float4*)&sQP[r * QP_STR + c4 * 4] = v;
    }
    __syncthreads();

    unsigned qa[8][4];
    #pragma unroll
    for (int ks = 0; ks < 8; ks++) {
        qa[ks][0] = __float_as_uint(sQP[(wm + g)     * QP_STR + ks * 8 + t]);
        qa[ks][1] = __float_as_uint(sQP[(wm + g + 8) * QP_STR + ks * 8 + t]);
        qa[ks][2] = __float_as_uint(sQP[(wm + g)     * QP_STR + ks * 8 + t + 4]);
        qa[ks][3] = __float_as_uint(sQP[(wm + g + 8) * QP_STR + ks * 8 + t + 4]);
    }
    __syncthreads();

    float m0 = -INFINITY, m1 = -INFINITY, l0 = 0.f, l1 = 0.f;
    float co[8][4] = {};

    for (int ch = 0; ch <= qt; ch++) {
        #pragma unroll
        for (int it = 0; it < 8; it++) {
            int idx = tid + it * 128;
            int r = idx >> 4, c4 = idx & 15;
            size_t base = ((size_t)(b * SEQ + ch * 64 + r)) * (2 * DMODEL) + h * DH + c4 * 4;
            float4 k4 = *(const float4*)&KV[base];
            float4 v4 = *(const float4*)&KV[base + DMODEL];
            *(float4*)&sK[r * KV_STR + c4 * 4] = k4;
            *(float4*)&sV[r * KV_STR + c4 * 4] = v4;
        }
        __syncthreads();

        float s[8][4] = {};
        #pragma unroll
        for (int ks = 0; ks < 8; ks++) {
            #pragma unroll
            for (int nf = 0; nf < 8; nf++) {
                unsigned b0 = __float_as_uint(sK[(nf * 8 + g) * KV_STR + ks * 8 + t]);
                unsigned b1 = __float_as_uint(sK[(nf * 8 + g) * KV_STR + ks * 8 + t + 4]);
                mma_tf32(s[nf], qa[ks][0], qa[ks][1], qa[ks][2], qa[ks][3], b0, b1);
            }
        }

        if (ch == qt) {
            int r0 = wm + g, r1 = wm + g + 8;
            #pragma unroll
            for (int nf = 0; nf < 8; nf++) {
                int col = nf * 8 + 2 * t;
                if (col     > r0) s[nf][0] = -1e30f;
                if (col + 1 > r0) s[nf][1] = -1e30f;
                if (col     > r1) s[nf][2] = -1e30f;
                if (col + 1 > r1) s[nf][3] = -1e30f;
            }
        }

        float mx0 = -1e30f, mx1 = -1e30f;
        #pragma unroll
        for (int nf = 0; nf < 8; nf++) {
            mx0 = fmaxf(mx0, fmaxf(s[nf][0], s[nf][1]));
            mx1 = fmaxf(mx1, fmaxf(s[nf][2], s[nf][3]));
        }
        mx0 = fmaxf(mx0, __shfl_xor_sync(0xffffffffu, mx0, 1));
        mx0 = fmaxf(mx0, __shfl_xor_sync(0xffffffffu, mx0, 2));
        mx1 = fmaxf(mx1, __shfl_xor_sync(0xffffffffu, mx1, 1));
        mx1 = fmaxf(mx1, __shfl_xor_sync(0xffffffffu, mx1, 2));
        float nm0 = fmaxf(m0, mx0), nm1 = fmaxf(m1, mx1);
        float sc0 = ex2(m0 - nm0), sc1 = ex2(m1 - nm1);
        m0 = nm0; m1 = nm1;
        float sum0 = 0.f, sum1 = 0.f;
        #pragma unroll
        for (int nf = 0; nf < 8; nf++) {
            s[nf][0] = ex2(s[nf][0] - m0); sum0 += s[nf][0];
            s[nf][1] = ex2(s[nf][1] - m0); sum0 += s[nf][1];
            s[nf][2] = ex2(s[nf][2] - m1); sum1 += s[nf][2];
            s[nf][3] = ex2(s[nf][3] - m1); sum1 += s[nf][3];
        }
        sum0 += __shfl_xor_sync(0xffffffffu, sum0, 1);
        sum0 += __shfl_xor_sync(0xffffffffu, sum0, 2);
        sum1 += __shfl_xor_sync(0xffffffffu, sum1, 1);
        sum1 += __shfl_xor_sync(0xffffffffu, sum1, 2);
        l0 = l0 * sc0 + sum0;
        l1 = l1 * sc1 + sum1;
        #pragma unroll
        for (int nf = 0; nf < 8; nf++) {
            co[nf][0] *= sc0; co[nf][1] *= sc0;
            co[nf][2] *= sc1; co[nf][3] *= sc1;
        }

        #pragma unroll
        for (int nf = 0; nf < 8; nf++) {
            int cbase = nf * 8 + 2 * t;
            sQP[(wm + g)     * QP_STR + cbase]     = __uint_as_float(f2tf(s[nf][0]));
            sQP[(wm + g)     * QP_STR + cbase + 1] = __uint_as_float(f2tf(s[nf][1]));
            sQP[(wm + g + 8) * QP_STR + cbase]     = __uint_as_float(f2tf(s[nf][2]));
            sQP[(wm + g + 8) * QP_STR + cbase + 1] = __uint_as_float(f2tf(s[nf][3]));
        }
        __syncwarp();

        #pragma unroll
        for (int ks = 0; ks < 8; ks++) {
            unsigned pa0 = __float_as_uint(sQP[(wm + g)     * QP_STR + ks * 8 + t]);
            unsigned pa1 = __float_as_uint(sQP[(wm + g + 8) * QP_STR + ks * 8 + t]);
            unsigned pa2 = __float_as_uint(sQP[(wm + g)     * QP_STR + ks * 8 + t + 4]);
            unsigned pa3 = __float_as_uint(sQP[(wm + g + 8) * QP_STR + ks * 8 + t + 4]);
            #pragma unroll
            for (int nf = 0; nf < 8; nf++) {
                unsigned b0 = __float_as_uint(sV[(ks * 8 + t)     * KV_STR + nf * 8 + g]);
                unsigned b1 = __float_as_uint(sV[(ks * 8 + t + 4) * KV_STR + nf * 8 + g]);
                mma_tf32(co[nf], pa0, pa1, pa2, pa3, b0, b1);
            }
        }
        __syncthreads();
    }

    float inv0 = 1.f / l0, inv1 = 1.f / l1;
    size_t row0 = (size_t)(b * SEQ + qrow0 + wm + g) * DMODEL + h * DH;
    size_t row1 = (size_t)(b * SEQ + qrow0 + wm + g + 8) * DMODEL + h * DH;
    #pragma unroll
    for (int nf = 0; nf < 8; nf++) {
        int cbase = nf * 8 + 2 * t;
        *(float2*)&O[row0 + cbase] = make_float2(co[nf][0] * inv0, co[nf][1] * inv0);
        *(float2*)&O[row1 + cbase] = make_float2(co[nf][2] * inv1, co[nf][3] * inv1);
    }
}

// ---------------- launch ----------------
extern "C" void kernel_launch(void* const* d_in, const int* in_sizes, int n_in,
                              void* d_out, int out_size)
{
    const float* x     = (const float*)d_in[0];
    const float* W_dq  = (const float*)d_in[1];
    const float* W_uq  = (const float*)d_in[2];
    const float* q_g   = (const float*)d_in[3];
    const float* q_b   = (const float*)d_in[4];
    const float* W_dkv = (const float*)d_in[5];
    const float* W_ukv = (const float*)d_in[6];
    const float* kv_g  = (const float*)d_in[7];
    const float* kv_b  = (const float*)d_in[8];
    const float* pq_g  = (const float*)d_in[9];
    const float* pq_b  = (const float*)d_in[10];
    const float* pk_g  = (const float*)d_in[11];
    const float* pk_b  = (const float*)d_in[12];
    const float* wo    = (const float*)d_in[13];
    float* out = (float*)d_out;

    float *xq, *xkv, *tq, *cq, *Qp, *tkv, *ckv, *KV, *attn, *woT;
    cudaGetSymbolAddress((void**)&xq,   g_xq);
    cudaGetSymbolAddress((void**)&xkv,  g_xkv);
    cudaGetSymbolAddress((void**)&tq,   g_tq);
    cudaGetSymbolAddress((void**)&cq,   g_cq);
    cudaGetSymbolAddress((void**)&Qp,   g_Q);
    cudaGetSymbolAddress((void**)&tkv,  g_tkv);
    cudaGetSymbolAddress((void**)&ckv,  g_ckv);
    cudaGetSymbolAddress((void**)&KV,   g_KV);
    cudaGetSymbolAddress((void**)&attn, g_attn);
    cudaGetSymbolAddress((void**)&woT,  g_woT);

    cudaFuncSetAttribute(attn_tc_kernel, cudaFuncAttributeMaxDynamicSharedMemorySize, ATT_SMEM);

    // 1. fused dual pre-LN (y=0) + wo transpose (y=1, independent work)
    prenorm_trans_kernel<<<dim3(MROWS, 2), 256>>>(
        x, pq_g, pq_b, pk_g, pk_b, xq, xkv, wo, woT);

    // 2. down-projections, batched (z-select): dq [4 x-tiles] + dkv [8 x-tiles]
    gemm_pair<false><<<dim3(KVPROJ / GBN, MROWS / GBM, 2), 256>>>(
        xq,  W_dq,  tq,  QPROJ,  DMODEL, 1.f, QPROJ / GBN,
        xkv, W_dkv, tkv, KVPROJ, DMODEL, 1.f, KVPROJ / GBN);

    // 3. the two inner LNs, batched
    ln_pair<<<dim3(MROWS, 2), 256>>>(
        tq,  q_g,  q_b,  cq,  QPROJ,
        tkv, kv_g, kv_b, ckv, KVPROJ);

    // 4. up-projections, batched (z-select): uq + ukv
    gemm_pair<true><<<dim3(2 * DMODEL / GBN, MROWS / GBM, 2), 256>>>(
        cq,  W_uq,  Qp, DMODEL,     QPROJ,  0.125f * LOG2E, DMODEL / GBN,
        ckv, W_ukv, KV, 2 * DMODEL, KVPROJ, 1.f,            2 * DMODEL / GBN);

    // 5. attention: longest-job-first grid (x = h,b fast; y = qt heavy-first)
    attn_tc_kernel<<<dim3(NH * BATCH, SEQ / 64), 128, ATT_SMEM>>>(Qp, KV, attn);

    // 6. output projection via pre-transposed woT (conflict-free non-TB path)
    gemm_tf32<false><<<dim3(DMODEL / GBN, MROWS / GBM), 256>>>(attn, woT, out, DMODEL, DMODEL, 1.f);
}

// round 17
// speedup vs baseline: 1.1678x; 1.0210x over previous
#include <cuda_runtime.h>
#include <math.h>
#include <stdint.h>

#define MROWS 4096
#define DMODEL 1024
#define QPROJ 512
#define KVPROJ 1024
#define NH 16
#define DH 64
#define SEQ 2048
#define BATCH 2
#define EPS 1e-5f
#define LOG2E 1.44269504088896340736f

// ---------------- scratch (no allocations allowed) ----------------
__device__ float g_xq  [MROWS * DMODEL];
__device__ float g_xkv [MROWS * DMODEL];
__device__ float g_tq  [MROWS * QPROJ];
__device__ float g_cq  [MROWS * QPROJ];
__device__ float g_Q   [MROWS * DMODEL];
__device__ float g_tkv [MROWS * KVPROJ];
__device__ float g_ckv [MROWS * KVPROJ];
__device__ float g_KV  [MROWS * 2 * DMODEL];
__device__ float g_attn[MROWS * DMODEL];
__device__ float g_woT [DMODEL * DMODEL];       // rounded transpose of wo
// tf32-pre-rounded weight copies (same [K][N] layout as inputs)
__device__ float g_Wdq [DMODEL * QPROJ];
__device__ float g_Wuq [QPROJ * DMODEL];
__device__ float g_Wdkv[DMODEL * KVPROJ];
__device__ float g_Wukv[KVPROJ * 2 * DMODEL];

// ---------------- tf32 helpers ----------------
__device__ __forceinline__ unsigned f2tf(float f) {
    unsigned u; asm("cvt.rna.tf32.f32 %0, %1;" : "=r"(u) : "f"(f)); return u;
}
__device__ __forceinline__ float rtf(float f) { return __uint_as_float(f2tf(f)); }
__device__ __forceinline__ float ex2(float x) {
    float r; asm("ex2.approx.f32 %0, %1;" : "=f"(r) : "f"(x)); return r;
}
__device__ __forceinline__ void mma_tf32(float c[4], unsigned a0, unsigned a1, unsigned a2, unsigned a3,
                                         unsigned b0, unsigned b1) {
    asm volatile(
        "mma.sync.aligned.m16n8k8.row.col.f32.tf32.tf32.f32 "
        "{%0,%1,%2,%3},{%4,%5,%6,%7},{%8,%9},{%0,%1,%2,%3};"
        : "+f"(c[0]), "+f"(c[1]), "+f"(c[2]), "+f"(c[3])
        : "r"(a0), "r"(a1), "r"(a2), "r"(a3), "r"(b0), "r"(b1));
}
__device__ __forceinline__ void ldsm4(unsigned& r0, unsigned& r1, unsigned& r2, unsigned& r3,
                                      uint32_t addr) {
    asm volatile("ldmatrix.sync.aligned.m8n8.x4.shared.b16 {%0,%1,%2,%3}, [%4];"
        : "=r"(r0), "=r"(r1), "=r"(r2), "=r"(r3) : "r"(addr));
}
__device__ __forceinline__ uint32_t smem_u32(const void* p) {
    uint32_t a;
    asm("{ .reg .u64 t; cvta.to.shared.u64 t, %1; cvt.u32.u64 %0, t; }" : "=r"(a) : "l"(p));
    return a;
}

// ---------------- block reduction (sum, sumsq), 256 threads ----------------
__device__ __forceinline__ float2 block_reduce2(float s, float q, float* sh) {
    #pragma unroll
    for (int o = 16; o; o >>= 1) {
        s += __shfl_xor_sync(0xffffffffu, s, o);
        q += __shfl_xor_sync(0xffffffffu, q, o);
    }
    int w = threadIdx.x >> 5;
    if ((threadIdx.x & 31) == 0) { sh[w] = s; sh[8 + w] = q; }
    __syncthreads();
    if (threadIdx.x < 32) {
        s = (threadIdx.x < 8) ? sh[threadIdx.x] : 0.f;
        q = (threadIdx.x < 8) ? sh[8 + threadIdx.x] : 0.f;
        #pragma unroll
        for (int o = 4; o; o >>= 1) {
            s += __shfl_xor_sync(0xffffffffu, s, o);
            q += __shfl_xor_sync(0xffffffffu, q, o);
        }
        if (threadIdx.x == 0) { sh[16] = s; sh[17] = q; }
    }
    __syncthreads();
    return make_float2(sh[16], sh[17]);
}

// ---------------- fused prep: pre-LN (y=0) + transpose/round weights (y=1) --
// y=0: blocks 0..4095 = prenorm rows (tf32-rounded outputs).
// y=1: blocks 0..1023 = wo transpose+round; 1024..5119 = weight round copies.
__global__ void __launch_bounds__(256) prep_kernel(
    const float* __restrict__ x,
    const float* __restrict__ pg, const float* __restrict__ pb,
    const float* __restrict__ kg, const float* __restrict__ kb,
    float* __restrict__ xq, float* __restrict__ xkv,
    const float* __restrict__ wo, float* __restrict__ woT,
    const float* __restrict__ Wdq, float* __restrict__ rdq,
    const float* __restrict__ Wuq, float* __restrict__ ruq,
    const float* __restrict__ Wdkv, float* __restrict__ rdkv,
    const float* __restrict__ Wukv, float* __restrict__ rukv)
{
    __shared__ float sh[32 * 33];
    if (blockIdx.y == 1) {
        int bx = blockIdx.x;
        if (bx < 1024) {   // wo transpose (rounded)
            int i0 = (bx & 31) * 32;       // k block
            int j0 = (bx >> 5) * 32;       // n block
            int tx = threadIdx.x & 31, ty = threadIdx.x >> 5;
            #pragma unroll
            for (int j = 0; j < 4; j++)
                sh[(ty + j * 8) * 33 + tx] = wo[(size_t)(j0 + ty + j * 8) * DMODEL + i0 + tx];
            __syncthreads();
            #pragma unroll
            for (int j = 0; j < 4; j++)
                woT[(size_t)(i0 + ty + j * 8) * DMODEL + j0 + tx] = rtf(sh[tx * 33 + ty + j * 8]);
            return;
        }
        // weight rounded copies: 1024 floats per block
        int w = bx - 1024;
        const float* src; float* dst; size_t off;
        if      (w < 512)  { src = Wdq;  dst = rdq;  off = (size_t)w * 1024; }
        else if (w < 1024) { src = Wuq;  dst = ruq;  off = (size_t)(w - 512) * 1024; }
        else if (w < 2048) { src = Wdkv; dst = rdkv; off = (size_t)(w - 1024) * 1024; }
        else               { src = Wukv; dst = rukv; off = (size_t)(w - 2048) * 1024; }
        size_t i = off + threadIdx.x * 4;
        float4 v = *(const float4*)&src[i];
        *(float4*)&dst[i] = make_float4(rtf(v.x), rtf(v.y), rtf(v.z), rtf(v.w));
        return;
    }
    int row = blockIdx.x;
    if (row >= MROWS) return;
    int i = threadIdx.x * 4;
    const float* xr = x + (size_t)row * DMODEL;
    float4 v = *(const float4*)&xr[i];
    float s = v.x + v.y + v.z + v.w;
    float q = v.x * v.x + v.y * v.y + v.z * v.z + v.w * v.w;
    float2 r = block_reduce2(s, q, sh);
    float mu = r.x * (1.f / DMODEL);
    float var = r.y * (1.f / DMODEL) - mu * mu;
    float inv = rsqrtf(var + EPS);
    float4 g1 = *(const float4*)&pg[i], b1 = *(const float4*)&pb[i];
    float4 g2 = *(const float4*)&kg[i], b2 = *(const float4*)&kb[i];
    float4 n = make_float4((v.x - mu) * inv, (v.y - mu) * inv, (v.z - mu) * inv, (v.w - mu) * inv);
    *(float4*)&xq [(size_t)row * DMODEL + i] = make_float4(
        rtf(n.x * g1.x + b1.x), rtf(n.y * g1.y + b1.y), rtf(n.z * g1.z + b1.z), rtf(n.w * g1.w + b1.w));
    *(float4*)&xkv[(size_t)row * DMODEL + i] = make_float4(
        rtf(n.x * g2.x + b2.x), rtf(n.y * g2.y + b2.y), rtf(n.z * g2.z + b2.z), rtf(n.w * g2.w + b2.w));
}

// ---------------- row LN core (tf32-rounded outputs) + batched pair ---------
__device__ __forceinline__ void ln_core(
    const float* __restrict__ x, const float* __restrict__ g,
    const float* __restrict__ b, float* __restrict__ y, int N, float* sh)
{
    int row = blockIdx.x;
    const float* xr = x + (size_t)row * N;
    float s = 0.f, q = 0.f;
    for (int i = threadIdx.x * 4; i < N; i += 1024) {
        float4 v = *(const float4*)&xr[i];
        s += v.x + v.y + v.z + v.w;
        q += v.x * v.x + v.y * v.y + v.z * v.z + v.w * v.w;
    }
    float2 r = block_reduce2(s, q, sh);
    float mu = r.x / N;
    float var = r.y / N - mu * mu;
    float inv = rsqrtf(var + EPS);
    for (int i = threadIdx.x * 4; i < N; i += 1024) {
        float4 v = *(const float4*)&xr[i];
        float4 gv = *(const float4*)&g[i], bv = *(const float4*)&b[i];
        *(float4*)&y[(size_t)row * N + i] = make_float4(
            rtf((v.x - mu) * inv * gv.x + bv.x), rtf((v.y - mu) * inv * gv.y + bv.y),
            rtf((v.z - mu) * inv * gv.z + bv.z), rtf((v.w - mu) * inv * gv.w + bv.w));
    }
}

__global__ void __launch_bounds__(256) ln_pair(
    const float* __restrict__ x0, const float* __restrict__ g0,
    const float* __restrict__ b0, float* __restrict__ y0, int N0,
    const float* __restrict__ x1, const float* __restrict__ g1,
    const float* __restrict__ b1, float* __restrict__ y1, int N1)
{
    __shared__ float sh[18];
    if (blockIdx.y == 0) ln_core(x0, g0, b0, y0, N0, sh);
    else                 ln_core(x1, g1, b1, y1, N1, sh);
}

// ---------------- tf32 tensor-core GEMM core ---------------------------------
// Operands tf32-pre-rounded in gmem -> storeT is a pure bit-copy (no cvt).
// A-fragments via ldmatrix.x4 (R9/R16-validated mapping).
#define GBM 128
#define GBN 128
#define GBK 32
#define ASTRIDE 516
#define BSTRIDE 136

template <bool ROUND>
__device__ __forceinline__ void gemm_core(
    unsigned* As, unsigned* Bs,
    const float* __restrict__ A, const float* __restrict__ B,
    float* __restrict__ C, int N, int K, float alpha)
{
    int tid = threadIdx.x;
    int m0 = blockIdx.y * GBM, n0 = blockIdx.x * GBN;
    int warp = tid >> 5, lane = tid & 31;
    int g = lane >> 2, t = lane & 3;
    int wm = (warp & 1) * 64, wn = (warp >> 1) * 32;

    int ar = tid >> 3, ac4 = tid & 7;
    int br = tid >> 5, bc4 = tid & 31;

    int row_off = ((lane >> 3) & 1) * 8 + (lane & 7);
    uint32_t abase = smem_u32(As)
                   + (uint32_t)((lane >> 4) * (ASTRIDE * 4) + (wm + row_off) * 16);

    float4 ra[4], rb[4];

    auto loadT = [&](int k0) {
        #pragma unroll
        for (int i = 0; i < 4; i++)
            ra[i] = *(const float4*)&A[(size_t)(m0 + ar + 32 * i) * K + k0 + ac4 * 4];
        #pragma unroll
        for (int i = 0; i < 4; i++)
            rb[i] = *(const float4*)&B[(size_t)(k0 + br + 8 * i) * N + n0 + bc4 * 4];
    };
    auto storeT = [&]() {
        #pragma unroll
        for (int i = 0; i < 4; i++)
            *(uint4*)&As[ac4 * ASTRIDE + (ar + 32 * i) * 4] = *(const uint4*)&ra[i];
        #pragma unroll
        for (int i = 0; i < 4; i++)
            *(uint4*)&Bs[(br + 8 * i) * BSTRIDE + bc4 * 4] = *(const uint4*)&rb[i];
    };

    float c[4][4][4] = {};

    loadT(0);
    storeT();
    __syncthreads();

    for (int k0 = GBK; ; k0 += GBK) {
        bool more = k0 < K;
        if (more) loadT(k0);

        #pragma unroll
        for (int ks = 0; ks < GBK; ks += 8) {
            unsigned bf[4][2];
            #pragma unroll
            for (int nf = 0; nf < 4; nf++) {
                bf[nf][0] = Bs[(ks + t) * BSTRIDE + wn + nf * 8 + g];
                bf[nf][1] = Bs[(ks + t + 4) * BSTRIDE + wn + nf * 8 + g];
            }
            #pragma unroll
            for (int mf = 0; mf < 4; mf++) {
                unsigned a0, a1, a2, a3;
                ldsm4(a0, a1, a2, a3,
                      abase + (uint32_t)mf * 256 + (uint32_t)(ks >> 2) * (ASTRIDE * 4));
                #pragma unroll
                for (int nf = 0; nf < 4; nf++)
                    mma_tf32(c[mf][nf], a0, a1, a2, a3, bf[nf][0], bf[nf][1]);
            }
        }
        if (!more) break;
        __syncthreads();
        storeT();
        __syncthreads();
    }

    auto outv = [&](float v) -> float {
        return ROUND ? rtf(alpha * v) : alpha * v;
    };
    #pragma unroll
    for (int mf = 0; mf < 4; mf++) {
        int r0 = m0 + wm + mf * 16 + g;
        #pragma unroll
        for (int nf = 0; nf < 4; nf++) {
            int cc = n0 + wn + nf * 8 + 2 * t;
            float2 lo = make_float2(outv(c[mf][nf][0]), outv(c[mf][nf][1]));
            float2 hi = make_float2(outv(c[mf][nf][2]), outv(c[mf][nf][3]));
            *(float2*)&C[(size_t)r0 * N + cc] = lo;
            *(float2*)&C[(size_t)(r0 + 8) * N + cc] = hi;
        }
    }
}

// solo gemm (wo, via pre-transposed+rounded woT)
template <bool ROUND>
__global__ void __launch_bounds__(256, 2) gemm_tf32(
    const float* __restrict__ A, const float* __restrict__ B,
    float* __restrict__ C, int N, int K, float alpha)
{
    __shared__ unsigned As[8 * ASTRIDE];
    __shared__ unsigned Bs[GBK * BSTRIDE];
    gemm_core<ROUND>(As, Bs, A, B, C, N, K, alpha);
}

// batched pair of independent GEMMs: blockIdx.z selects. Inactive x-tiles exit.
template <bool ROUND>
__global__ void __launch_bounds__(256, 2) gemm_pair(
    const float* __restrict__ A0, const float* __restrict__ B0, float* __restrict__ C0,
    int N0, int K0, float al0, int nx0,
    const float* __restrict__ A1, const float* __restrict__ B1, float* __restrict__ C1,
    int N1, int K1, float al1, int nx1)
{
    __shared__ unsigned As[8 * ASTRIDE];
    __shared__ unsigned Bs[GBK * BSTRIDE];
    if (blockIdx.z == 0) {
        if ((int)blockIdx.x >= nx0) return;
        gemm_core<ROUND>(As, Bs, A0, B0, C0, N0, K0, al0);
    } else {
        if ((int)blockIdx.x >= nx1) return;
        gemm_core<ROUND>(As, Bs, A1, B1, C1, N1, K1, al1);
    }
}

// ---------------- tensor-core causal flash attention (R15 core) --------------
// Grid: x = h*BATCH + b (fast), y = qt with heavy tiles first (slow) — LJF.
// Epilogue outputs tf32-rounded (exact operand for the wo gemm).
#define QP_STR 68
#define KV_STR 76
#define ATT_SMEM ((64 * QP_STR + 2 * 64 * KV_STR) * 4)

extern __shared__ float att_sm[];

__global__ void __launch_bounds__(128) attn_tc_kernel(
    const float* __restrict__ Q, const float* __restrict__ KV, float* __restrict__ O)
{
    float* sQP = att_sm;
    float* sK  = sQP + 64 * QP_STR;
    float* sV  = sK  + 64 * KV_STR;

    int tid = threadIdx.x, warp = tid >> 5, lane = tid & 31;
    int g = lane >> 2, t = lane & 3;
    int wm = warp * 16;
    int hb = blockIdx.x;
    int h = hb >> 1, b = hb & 1;
    int qt = (int)gridDim.y - 1 - (int)blockIdx.y;   // heavy (large qt) first
    int qrow0 = qt * 64;

    #pragma unroll
    for (int it = 0; it < 8; it++) {
        int idx = tid + it * 128;
        int r = idx >> 4, c4 = idx & 15;
        float4 v = *(const float4*)&Q[((size_t)(b * SEQ + qrow0 + r)) * DMODEL + h * DH + c4 * 4];
        *(float4*)&sQP[r * QP_STR + c4 * 4] = v;
    }
    __syncthreads();

    unsigned qa[8][4];
    #pragma unroll
    for (int ks = 0; ks < 8; ks++) {
        qa[ks][0] = __float_as_uint(sQP[(wm + g)     * QP_STR + ks * 8 + t]);
        qa[ks][1] = __float_as_uint(sQP[(wm + g + 8) * QP_STR + ks * 8 + t]);
        qa[ks][2] = __float_as_uint(sQP[(wm + g)     * QP_STR + ks * 8 + t + 4]);
        qa[ks][3] = __float_as_uint(sQP[(wm + g + 8) * QP_STR + ks * 8 + t + 4]);
    }
    __syncthreads();

    float m0 = -INFINITY, m1 = -INFINITY, l0 = 0.f, l1 = 0.f;
    float co[8][4] = {};

    for (int ch = 0; ch <= qt; ch++) {
        #pragma unroll
        for (int it = 0; it < 8; it++) {
            int idx = tid + it * 128;
            int r = idx >> 4, c4 = idx & 15;
            size_t base = ((size_t)(b * SEQ + ch * 64 + r)) * (2 * DMODEL) + h * DH + c4 * 4;
            float4 k4 = *(const float4*)&KV[base];
            float4 v4 = *(const float4*)&KV[base + DMODEL];
            *(float4*)&sK[r * KV_STR + c4 * 4] = k4;
            *(float4*)&sV[r * KV_STR + c4 * 4] = v4;
        }
        __syncthreads();

        float s[8][4] = {};
        #pragma unroll
        for (int ks = 0; ks < 8; ks++) {
            #pragma unroll
            for (int nf = 0; nf < 8; nf++) {
                unsigned b0 = __float_as_uint(sK[(nf * 8 + g) * KV_STR + ks * 8 + t]);
                unsigned b1 = __float_as_uint(sK[(nf * 8 + g) * KV_STR + ks * 8 + t + 4]);
                mma_tf32(s[nf], qa[ks][0], qa[ks][1], qa[ks][2], qa[ks][3], b0, b1);
            }
        }

        if (ch == qt) {
            int r0 = wm + g, r1 = wm + g + 8;
            #pragma unroll
            for (int nf = 0; nf < 8; nf++) {
                int col = nf * 8 + 2 * t;
                if (col     > r0) s[nf][0] = -1e30f;
                if (col + 1 > r0) s[nf][1] = -1e30f;
                if (col     > r1) s[nf][2] = -1e30f;
                if (col + 1 > r1) s[nf][3] = -1e30f;
            }
        }

        float mx0 = -1e30f, mx1 = -1e30f;
        #pragma unroll
        for (int nf = 0; nf < 8; nf++) {
            mx0 = fmaxf(mx0, fmaxf(s[nf][0], s[nf][1]));
            mx1 = fmaxf(mx1, fmaxf(s[nf][2], s[nf][3]));
        }
        mx0 = fmaxf(mx0, __shfl_xor_sync(0xffffffffu, mx0, 1));
        mx0 = fmaxf(mx0, __shfl_xor_sync(0xffffffffu, mx0, 2));
        mx1 = fmaxf(mx1, __shfl_xor_sync(0xffffffffu, mx1, 1));
        mx1 = fmaxf(mx1, __shfl_xor_sync(0xffffffffu, mx1, 2));
        float nm0 = fmaxf(m0, mx0), nm1 = fmaxf(m1, mx1);
        float sc0 = ex2(m0 - nm0), sc1 = ex2(m1 - nm1);
        m0 = nm0; m1 = nm1;
        float sum0 = 0.f, sum1 = 0.f;
        #pragma unroll
        for (int nf = 0; nf < 8; nf++) {
            s[nf][0] = ex2(s[nf][0] - m0); sum0 += s[nf][0];
            s[nf][1] = ex2(s[nf][1] - m0); sum0 += s[nf][1];
            s[nf][2] = ex2(s[nf][2] - m1); sum1 += s[nf][2];
            s[nf][3] = ex2(s[nf][3] - m1); sum1 += s[nf][3];
        }
        sum0 += __shfl_xor_sync(0xffffffffu, sum0, 1);
        sum0 += __shfl_xor_sync(0xffffffffu, sum0, 2);
        sum1 += __shfl_xor_sync(0xffffffffu, sum1, 1);
        sum1 += __shfl_xor_sync(0xffffffffu, sum1, 2);
        l0 = l0 * sc0 + sum0;
        l1 = l1 * sc1 + sum1;
        #pragma unroll
        for (int nf = 0; nf < 8; nf++) {
            co[nf][0] *= sc0; co[nf][1] *= sc0;
            co[nf][2] *= sc1; co[nf][3] *= sc1;
        }

        #pragma unroll
        for (int nf = 0; nf < 8; nf++) {
            int cbase = nf * 8 + 2 * t;
            sQP[(wm + g)     * QP_STR + cbase]     = __uint_as_float(f2tf(s[nf][0]));
            sQP[(wm + g)     * QP_STR + cbase + 1] = __uint_as_float(f2tf(s[nf][1]));
            sQP[(wm + g + 8) * QP_STR + cbase]     = __uint_as_float(f2tf(s[nf][2]));
            sQP[(wm + g + 8) * QP_STR + cbase + 1] = __uint_as_float(f2tf(s[nf][3]));
        }
        __syncwarp();

        #pragma unroll
        for (int ks = 0; ks < 8; ks++) {
            unsigned pa0 = __float_as_uint(sQP[(wm + g)     * QP_STR + ks * 8 + t]);
            unsigned pa1 = __float_as_uint(sQP[(wm + g + 8) * QP_STR + ks * 8 + t]);
            unsigned pa2 = __float_as_uint(sQP[(wm + g)     * QP_STR + ks * 8 + t + 4]);
            unsigned pa3 = __float_as_uint(sQP[(wm + g + 8) * QP_STR + ks * 8 + t + 4]);
            #pragma unroll
            for (int nf = 0; nf < 8; nf++) {
                unsigned b0 = __float_as_uint(sV[(ks * 8 + t)     * KV_STR + nf * 8 + g]);
                unsigned b1 = __float_as_uint(sV[(ks * 8 + t + 4) * KV_STR + nf * 8 + g]);
                mma_tf32(co[nf], pa0, pa1, pa2, pa3, b0, b1);
            }
        }
        __syncthreads();
    }

    float inv0 = 1.f / l0, inv1 = 1.f / l1;
    size_t row0 = (size_t)(b * SEQ + qrow0 + wm + g) * DMODEL + h * DH;
    size_t row1 = (size_t)(b * SEQ + qrow0 + wm + g + 8) * DMODEL + h * DH;
    #pragma unroll
    for (int nf = 0; nf < 8; nf++) {
        int cbase = nf * 8 + 2 * t;
        *(float2*)&O[row0 + cbase] = make_float2(rtf(co[nf][0] * inv0), rtf(co[nf][1] * inv0));
        *(float2*)&O[row1 + cbase] = make_float2(rtf(co[nf][2] * inv1), rtf(co[nf][3] * inv1));
    }
}

// ---------------- launch ----------------
extern "C" void kernel_launch(void* const* d_in, const int* in_sizes, int n_in,
                              void* d_out, int out_size)
{
    const float* x     = (const float*)d_in[0];
    const float* W_dq  = (const float*)d_in[1];
    const float* W_uq  = (const float*)d_in[2];
    const float* q_g   = (const float*)d_in[3];
    const float* q_b   = (const float*)d_in[4];
    const float* W_dkv = (const float*)d_in[5];
    const float* W_ukv = (const float*)d_in[6];
    const float* kv_g  = (const float*)d_in[7];
    const float* kv_b  = (const float*)d_in[8];
    const float* pq_g  = (const float*)d_in[9];
    const float* pq_b  = (const float*)d_in[10];
    const float* pk_g  = (const float*)d_in[11];
    const float* pk_b  = (const float*)d_in[12];
    const float* wo    = (const float*)d_in[13];
    float* out = (float*)d_out;

    float *xq, *xkv, *tq, *cq, *Qp, *tkv, *ckv, *KV, *attn, *woT;
    float *rdq, *ruq, *rdkv, *rukv;
    cudaGetSymbolAddress((void**)&xq,   g_xq);
    cudaGetSymbolAddress((void**)&xkv,  g_xkv);
    cudaGetSymbolAddress((void**)&tq,   g_tq);
    cudaGetSymbolAddress((void**)&cq,   g_cq);
    cudaGetSymbolAddress((void**)&Qp,   g_Q);
    cudaGetSymbolAddress((void**)&tkv,  g_tkv);
    cudaGetSymbolAddress((void**)&ckv,  g_ckv);
    cudaGetSymbolAddress((void**)&KV,   g_KV);
    cudaGetSymbolAddress((void**)&attn, g_attn);
    cudaGetSymbolAddress((void**)&woT,  g_woT);
    cudaGetSymbolAddress((void**)&rdq,  g_Wdq);
    cudaGetSymbolAddress((void**)&ruq,  g_Wuq);
    cudaGetSymbolAddress((void**)&rdkv, g_Wdkv);
    cudaGetSymbolAddress((void**)&rukv, g_Wukv);

    cudaFuncSetAttribute(attn_tc_kernel, cudaFuncAttributeMaxDynamicSharedMemorySize, ATT_SMEM);

    // 1. fused prep: prenorm rows (y=0) + wo transpose & weight rounding (y=1)
    prep_kernel<<<dim3(5120, 2), 256>>>(
        x, pq_g, pq_b, pk_g, pk_b, xq, xkv,
        wo, woT, W_dq, rdq, W_uq, ruq, W_dkv, rdkv, W_ukv, rukv);

    // 2. down-projections, batched (z-select): dq [4 x-tiles] + dkv [8 x-tiles]
    gemm_pair<false><<<dim3(KVPROJ / GBN, MROWS / GBM, 2), 256>>>(
        xq,  rdq,  tq,  QPROJ,  DMODEL, 1.f, QPROJ / GBN,
        xkv, rdkv, tkv, KVPROJ, DMODEL, 1.f, KVPROJ / GBN);

    // 3. the two inner LNs, batched (tf32-rounded outputs)
    ln_pair<<<dim3(MROWS, 2), 256>>>(
        tq,  q_g,  q_b,  cq,  QPROJ,
        tkv, kv_g, kv_b, ckv, KVPROJ);

    // 4. up-projections, batched (z-select): uq + ukv
    gemm_pair<true><<<dim3(2 * DMODEL / GBN, MROWS / GBM, 2), 256>>>(
        cq,  ruq,  Qp, DMODEL,     QPROJ,  0.125f * LOG2E, DMODEL / GBN,
        ckv, rukv, KV, 2 * DMODEL, KVPROJ, 1.f,            2 * DMODEL / GBN);

    // 5. attention: longest-job-first grid (x = h,b fast; y = qt heavy-first)
    attn_tc_kernel<<<dim3(NH * BATCH, SEQ / 64), 128, ATT_SMEM>>>(Qp, KV, attn);

    // 6. output projection via pre-transposed+rounded woT
    gemm_tf32<false><<<dim3(DMODEL / GBN, MROWS / GBM), 256>>>(attn, woT, out, DMODEL, DMODEL, 1.f);
}